// round 1
// baseline (speedup 1.0000x reference)
#include <cuda_runtime.h>
#include <cuda_bf16.h>
#include <math.h>

// Problem constants
#define BATCH 2
#define SEQ   2048
#define EMBED 1024
#define HEADS 16
#define HDIM  64     // EMBED / HEADS
#define MROWS (BATCH * SEQ)   // 4096

// ---------------- scratch (device globals; no runtime allocation) ----------
__device__ float g_Qp[MROWS * EMBED];
__device__ float g_Kp[MROWS * EMBED];
__device__ float g_Vp[MROWS * EMBED];
__device__ float g_Attn[MROWS * EMBED];

// ---------------- SGEMM: C = A[M,K] @ B[K,N] + bias[N] ---------------------
#define BM 128
#define BN 128
#define BK 16
#define TM 8
#define TN 8

__global__ __launch_bounds__(256)
void sgemm_bias_kernel(const float* __restrict__ A,
                       const float* __restrict__ B,
                       const float* __restrict__ bias,
                       float* __restrict__ C,
                       int M, int N, int K)
{
    __shared__ float As[BK][BM];   // A tile stored transposed: As[k][m]
    __shared__ float Bs[BK][BN];

    const int tid  = threadIdx.x;          // 0..255
    const int trow = tid >> 4;             // 0..15
    const int tcol = tid & 15;             // 0..15
    const int brow = blockIdx.y;
    const int bcol = blockIdx.x;

    const float* Aptr = A + (size_t)brow * BM * K;
    const float* Bptr = B + (size_t)bcol * BN;

    float acc[TM][TN];
    #pragma unroll
    for (int i = 0; i < TM; i++)
        #pragma unroll
        for (int j = 0; j < TN; j++) acc[i][j] = 0.0f;

    for (int k0 = 0; k0 < K; k0 += BK) {
        // ---- load A tile: 128 rows x 16 cols = 512 float4; 2 per thread ----
        #pragma unroll
        for (int i = 0; i < 2; i++) {
            int f  = tid + i * 256;        // 0..511
            int r  = f >> 2;               // 0..127
            int c4 = f & 3;                // 0..3
            float4 v = *(const float4*)(Aptr + (size_t)r * K + k0 + c4 * 4);
            As[c4 * 4 + 0][r] = v.x;
            As[c4 * 4 + 1][r] = v.y;
            As[c4 * 4 + 2][r] = v.z;
            As[c4 * 4 + 3][r] = v.w;
        }
        // ---- load B tile: 16 rows x 128 cols = 512 float4; 2 per thread ----
        #pragma unroll
        for (int i = 0; i < 2; i++) {
            int f  = tid + i * 256;
            int r  = f >> 5;               // 0..15
            int c4 = f & 31;               // 0..31
            *(float4*)(&Bs[r][c4 * 4]) =
                *(const float4*)(Bptr + (size_t)(k0 + r) * N + c4 * 4);
        }
        __syncthreads();

        #pragma unroll
        for (int kk = 0; kk < BK; kk++) {
            float a[TM], b[TN];
            float4 a0 = *(const float4*)(&As[kk][trow * TM + 0]);
            float4 a1 = *(const float4*)(&As[kk][trow * TM + 4]);
            float4 b0 = *(const float4*)(&Bs[kk][tcol * TN + 0]);
            float4 b1 = *(const float4*)(&Bs[kk][tcol * TN + 4]);
            a[0]=a0.x; a[1]=a0.y; a[2]=a0.z; a[3]=a0.w;
            a[4]=a1.x; a[5]=a1.y; a[6]=a1.z; a[7]=a1.w;
            b[0]=b0.x; b[1]=b0.y; b[2]=b0.z; b[3]=b0.w;
            b[4]=b1.x; b[5]=b1.y; b[6]=b1.z; b[7]=b1.w;
            #pragma unroll
            for (int i = 0; i < TM; i++)
                #pragma unroll
                for (int j = 0; j < TN; j++)
                    acc[i][j] = fmaf(a[i], b[j], acc[i][j]);
        }
        __syncthreads();
    }

    // ---- epilogue: bias + store ----
    #pragma unroll
    for (int i = 0; i < TM; i++) {
        int row = brow * BM + trow * TM + i;
        #pragma unroll
        for (int j = 0; j < TN; j += 4) {
            int col = bcol * BN + tcol * TN + j;
            float4 o;
            o.x = acc[i][j + 0] + bias[col + 0];
            o.y = acc[i][j + 1] + bias[col + 1];
            o.z = acc[i][j + 2] + bias[col + 2];
            o.w = acc[i][j + 3] + bias[col + 3];
            *(float4*)(C + (size_t)row * N + col) = o;
        }
    }
}

// ---------------- Flash attention (fp32, online softmax) -------------------
// One thread per query row. 128 queries / block. K/V tiles of 64 keys in SMEM.
#define QB 128
#define KT 64

__device__ __forceinline__ float dot4(float4 a, float4 b) {
    return a.x * b.x + a.y * b.y + a.z * b.z + a.w * b.w;
}

__global__ __launch_bounds__(QB, 3)
void attn_kernel(const float* __restrict__ Qp,
                 const float* __restrict__ Kp,
                 const float* __restrict__ Vp,
                 float* __restrict__ Out)
{
    __shared__ float Ks[KT][HDIM];
    __shared__ float Vs[KT][HDIM];

    const int h  = blockIdx.y;              // head
    const int bb = blockIdx.z;              // batch
    const int t  = threadIdx.x;             // 0..127
    const int qi = blockIdx.x * QB + t;     // query row within sequence

    // 1/sqrt(64) * log2(e): softmax computed in log2-domain (single MUFU.EX2)
    const float scale = 0.125f * 1.4426950408889634f;

    const float* qrow = Qp + ((size_t)(bb * SEQ + qi)) * EMBED + h * HDIM;
    float4 q4[16];
    #pragma unroll
    for (int i = 0; i < 16; i++) q4[i] = ((const float4*)qrow)[i];

    float4 o4[16];
    #pragma unroll
    for (int i = 0; i < 16; i++) o4[i] = make_float4(0.f, 0.f, 0.f, 0.f);
    float mval = -1e30f, l = 0.0f;

    const float* Kbase = Kp + ((size_t)bb * SEQ) * EMBED + h * HDIM;
    const float* Vbase = Vp + ((size_t)bb * SEQ) * EMBED + h * HDIM;

    for (int k0 = 0; k0 < SEQ; k0 += KT) {
        __syncthreads();   // all threads done with previous tile
        // load K,V tiles: 64 rows x 16 float4 each; 8 float4 per thread per tile
        #pragma unroll
        for (int i = 0; i < 8; i++) {
            int f = t + i * QB;        // 0..1023
            int r = f >> 4;            // key row 0..63
            int c = f & 15;            // float4 col 0..15
            ((float4*)Ks)[f] = ((const float4*)(Kbase + (size_t)(k0 + r) * EMBED))[c];
            ((float4*)Vs)[f] = ((const float4*)(Vbase + (size_t)(k0 + r) * EMBED))[c];
        }
        __syncthreads();

        for (int kk = 0; kk < KT; kk++) {
            const float4* krow = (const float4*)Ks[kk];
            float s0 = 0.f, s1 = 0.f, s2 = 0.f, s3 = 0.f;
            #pragma unroll
            for (int i = 0; i < 16; i += 4) {
                s0 += dot4(q4[i + 0], krow[i + 0]);
                s1 += dot4(q4[i + 1], krow[i + 1]);
                s2 += dot4(q4[i + 2], krow[i + 2]);
                s3 += dot4(q4[i + 3], krow[i + 3]);
            }
            float s = ((s0 + s1) + (s2 + s3)) * scale;   // log2-domain logit

            if (s > mval) {
                float corr = exp2f(mval - s);   // 0 on first key (mval=-1e30)
                mval = s;
                l *= corr;
                #pragma unroll
                for (int i = 0; i < 16; i++) {
                    o4[i].x *= corr; o4[i].y *= corr;
                    o4[i].z *= corr; o4[i].w *= corr;
                }
            }
            float p = exp2f(s - mval);
            l += p;

            const float4* vrow = (const float4*)Vs[kk];
            #pragma unroll
            for (int i = 0; i < 16; i++) {
                float4 vv = vrow[i];
                o4[i].x = fmaf(p, vv.x, o4[i].x);
                o4[i].y = fmaf(p, vv.y, o4[i].y);
                o4[i].z = fmaf(p, vv.z, o4[i].z);
                o4[i].w = fmaf(p, vv.w, o4[i].w);
            }
        }
    }

    const float inv = 1.0f / l;
    float* orow = Out + ((size_t)(bb * SEQ + qi)) * EMBED + h * HDIM;
    #pragma unroll
    for (int i = 0; i < 16; i++) {
        float4 ov;
        ov.x = o4[i].x * inv; ov.y = o4[i].y * inv;
        ov.z = o4[i].z * inv; ov.w = o4[i].w * inv;
        ((float4*)orow)[i] = ov;
    }
}

// ---------------- launch ----------------------------------------------------
extern "C" void kernel_launch(void* const* d_in, const int* in_sizes, int n_in,
                              void* d_out, int out_size)
{
    const float* q  = (const float*)d_in[0];
    const float* k  = (const float*)d_in[1];
    const float* v  = (const float*)d_in[2];
    const float* Wq = (const float*)d_in[3];
    const float* bq = (const float*)d_in[4];
    const float* Wk = (const float*)d_in[5];
    const float* bk = (const float*)d_in[6];
    const float* Wv = (const float*)d_in[7];
    const float* bv = (const float*)d_in[8];
    const float* Wo = (const float*)d_in[9];
    const float* bo = (const float*)d_in[10];
    float* out = (float*)d_out;

    float *Qp, *Kp, *Vp, *Attn;
    cudaGetSymbolAddress((void**)&Qp,   g_Qp);
    cudaGetSymbolAddress((void**)&Kp,   g_Kp);
    cudaGetSymbolAddress((void**)&Vp,   g_Vp);
    cudaGetSymbolAddress((void**)&Attn, g_Attn);

    dim3 gemm_grid(EMBED / BN, MROWS / BM);   // (8, 32)
    sgemm_bias_kernel<<<gemm_grid, 256>>>(q, Wq, bq, Qp, MROWS, EMBED, EMBED);
    sgemm_bias_kernel<<<gemm_grid, 256>>>(k, Wk, bk, Kp, MROWS, EMBED, EMBED);
    sgemm_bias_kernel<<<gemm_grid, 256>>>(v, Wv, bv, Vp, MROWS, EMBED, EMBED);

    dim3 attn_grid(SEQ / QB, HEADS, BATCH);   // (16, 16, 2)
    attn_kernel<<<attn_grid, QB>>>(Qp, Kp, Vp, Attn);

    sgemm_bias_kernel<<<gemm_grid, 256>>>(Attn, Wo, bo, out, MROWS, EMBED, EMBED);
}

// round 2
// speedup vs baseline: 1.2883x; 1.2883x over previous
#include <cuda_runtime.h>
#include <cuda_bf16.h>
#include <math.h>
#include <stdint.h>

// Problem constants
#define BATCH 2
#define SEQ   2048
#define EMBED 1024
#define HEADS 16
#define HDIM  64
#define MROWS (BATCH * SEQ)   // 4096

// ---------------- scratch (device globals; no runtime allocation) ----------
__device__ float g_Qp[MROWS * EMBED];
__device__ float g_Kp[MROWS * EMBED];
__device__ float g_Vp[MROWS * EMBED];
__device__ float g_Attn[MROWS * EMBED];

// ---------------- helpers ---------------------------------------------------
__device__ __forceinline__ uint32_t f2tf32(float x) {
    uint32_t r;
    asm("cvt.rna.tf32.f32 %0, %1;" : "=r"(r) : "f"(x));
    return r;
}

__device__ __forceinline__ void cp_async16(void* smem_ptr, const void* gmem_ptr) {
    uint32_t s = (uint32_t)__cvta_generic_to_shared(smem_ptr);
    asm volatile("cp.async.cg.shared.global [%0], [%1], 16;\n" :: "r"(s), "l"(gmem_ptr));
}
#define CP_ASYNC_COMMIT() asm volatile("cp.async.commit_group;\n" ::: "memory")
#define CP_ASYNC_WAIT0()  asm volatile("cp.async.wait_group 0;\n" ::: "memory")

__device__ __forceinline__ void mma_tf32(float& d0, float& d1, float& d2, float& d3,
                                         uint32_t a0, uint32_t a1, uint32_t a2, uint32_t a3,
                                         uint32_t b0, uint32_t b1) {
    asm volatile(
        "mma.sync.aligned.m16n8k8.row.col.f32.tf32.tf32.f32 "
        "{%0,%1,%2,%3}, {%4,%5,%6,%7}, {%8,%9}, {%0,%1,%2,%3};\n"
        : "+f"(d0), "+f"(d1), "+f"(d2), "+f"(d3)
        : "r"(a0), "r"(a1), "r"(a2), "r"(a3), "r"(b0), "r"(b1));
}

// ---------------- TF32 tensor-core GEMM: C = A[M,K] @ B[K,N] + bias[N] -----
// Block tile 128x128xBK16, 8 warps (2 x 4), warp tile 64x32, m16n8k8 MMAs.
#define GBM 128
#define GBN 128
#define GBK 16
#define A_STRIDE (GBK + 4)   // 20 floats -> conflict-free a-frag LDS
#define B_STRIDE (GBN + 8)   // 136 floats -> conflict-free b-frag LDS

__global__ __launch_bounds__(256, 2)
void gemm_tf32_bias(const float* __restrict__ A,
                    const float* __restrict__ B,
                    const float* __restrict__ bias,
                    float* __restrict__ C,
                    int M, int N, int K)
{
    __shared__ float As[2][GBM * A_STRIDE];   // [m][k] padded
    __shared__ float Bs[2][GBK * B_STRIDE];   // [k][n] padded

    const int tid  = threadIdx.x;
    const int wid  = tid >> 5;
    const int lane = tid & 31;
    const int gi   = lane >> 2;   // group id 0..7
    const int ti   = lane & 3;    // thread-in-group 0..3

    const int brow = blockIdx.y;
    const int bcol = blockIdx.x;
    const int warp_m = (wid & 1) * 64;   // 0 or 64
    const int warp_n = (wid >> 1) * 32;  // 0,32,64,96

    const float* Ablk = A + (size_t)brow * GBM * K;
    const float* Bblk = B + (size_t)bcol * GBN;

    float acc[4][4][4];
    #pragma unroll
    for (int i = 0; i < 4; i++)
        #pragma unroll
        for (int j = 0; j < 4; j++)
            #pragma unroll
            for (int r = 0; r < 4; r++) acc[i][j][r] = 0.0f;

    // per-thread load coordinates (2 x 16B each for A and B per tile)
    // A tile: 128 rows x 16 floats = 512 float4
    // B tile: 16 rows x 128 floats = 512 float4
    const int NIT = K / GBK;

    auto load_tile = [&](int buf, int k0) {
        #pragma unroll
        for (int i = 0; i < 2; i++) {
            int f  = tid + i * 256;       // 0..511
            int r  = f >> 2;              // 0..127
            int c4 = f & 3;               // 0..3
            cp_async16(&As[buf][r * A_STRIDE + c4 * 4],
                       Ablk + (size_t)r * K + k0 + c4 * 4);
        }
        #pragma unroll
        for (int i = 0; i < 2; i++) {
            int f  = tid + i * 256;
            int r  = f >> 5;              // 0..15
            int c4 = f & 31;              // 0..31
            cp_async16(&Bs[buf][r * B_STRIDE + c4 * 4],
                       Bblk + (size_t)(k0 + r) * N + c4 * 4);
        }
        CP_ASYNC_COMMIT();
    };

    load_tile(0, 0);

    int buf = 0;
    for (int it = 0; it < NIT; it++) {
        CP_ASYNC_WAIT0();
        __syncthreads();
        if (it + 1 < NIT) load_tile(buf ^ 1, (it + 1) * GBK);

        const float* Asb = As[buf];
        const float* Bsb = Bs[buf];
        #pragma unroll
        for (int ks = 0; ks < GBK; ks += 8) {
            uint32_t afr[4][4];
            #pragma unroll
            for (int mt = 0; mt < 4; mt++) {
                int row = warp_m + mt * 16 + gi;
                int col = ks + ti;
                afr[mt][0] = f2tf32(Asb[row * A_STRIDE + col]);
                afr[mt][1] = f2tf32(Asb[(row + 8) * A_STRIDE + col]);
                afr[mt][2] = f2tf32(Asb[row * A_STRIDE + col + 4]);
                afr[mt][3] = f2tf32(Asb[(row + 8) * A_STRIDE + col + 4]);
            }
            uint32_t bfr[4][2];
            #pragma unroll
            for (int nt = 0; nt < 4; nt++) {
                int coln = warp_n + nt * 8 + gi;
                int rowk = ks + ti;
                bfr[nt][0] = f2tf32(Bsb[rowk * B_STRIDE + coln]);
                bfr[nt][1] = f2tf32(Bsb[(rowk + 4) * B_STRIDE + coln]);
            }
            #pragma unroll
            for (int mt = 0; mt < 4; mt++)
                #pragma unroll
                for (int nt = 0; nt < 4; nt++)
                    mma_tf32(acc[mt][nt][0], acc[mt][nt][1],
                             acc[mt][nt][2], acc[mt][nt][3],
                             afr[mt][0], afr[mt][1], afr[mt][2], afr[mt][3],
                             bfr[nt][0], bfr[nt][1]);
        }
        buf ^= 1;
        __syncthreads();
    }

    // epilogue: bias + store (c0: [gi][2*ti], c1: +1col, c2: +8row, c3: both)
    #pragma unroll
    for (int mt = 0; mt < 4; mt++) {
        int row0 = brow * GBM + warp_m + mt * 16 + gi;
        #pragma unroll
        for (int nt = 0; nt < 4; nt++) {
            int col0 = bcol * GBN + warp_n + nt * 8 + 2 * ti;
            float b0 = bias[col0], b1 = bias[col0 + 1];
            float2 v0 = make_float2(acc[mt][nt][0] + b0, acc[mt][nt][1] + b1);
            float2 v1 = make_float2(acc[mt][nt][2] + b0, acc[mt][nt][3] + b1);
            *(float2*)(C + (size_t)row0 * N + col0) = v0;
            *(float2*)(C + (size_t)(row0 + 8) * N + col0) = v1;
        }
    }
}

// ---------------- Flash attention (fp32, online softmax) -------------------
#define QB 128
#define KT 64

__device__ __forceinline__ float dot4(float4 a, float4 b) {
    return a.x * b.x + a.y * b.y + a.z * b.z + a.w * b.w;
}

__global__ __launch_bounds__(QB, 3)
void attn_kernel(const float* __restrict__ Qp,
                 const float* __restrict__ Kp,
                 const float* __restrict__ Vp,
                 float* __restrict__ Out)
{
    __shared__ float Ks[KT][HDIM];
    __shared__ float Vs[KT][HDIM];

    const int h  = blockIdx.y;
    const int bb = blockIdx.z;
    const int t  = threadIdx.x;
    const int qi = blockIdx.x * QB + t;

    const float scale = 0.125f * 1.4426950408889634f;

    const float* qrow = Qp + ((size_t)(bb * SEQ + qi)) * EMBED + h * HDIM;
    float4 q4[16];
    #pragma unroll
    for (int i = 0; i < 16; i++) q4[i] = ((const float4*)qrow)[i];

    float4 o4[16];
    #pragma unroll
    for (int i = 0; i < 16; i++) o4[i] = make_float4(0.f, 0.f, 0.f, 0.f);
    float mval = -1e30f, l = 0.0f;

    const float* Kbase = Kp + ((size_t)bb * SEQ) * EMBED + h * HDIM;
    const float* Vbase = Vp + ((size_t)bb * SEQ) * EMBED + h * HDIM;

    for (int k0 = 0; k0 < SEQ; k0 += KT) {
        __syncthreads();
        #pragma unroll
        for (int i = 0; i < 8; i++) {
            int f = t + i * QB;
            int r = f >> 4;
            int c = f & 15;
            ((float4*)Ks)[f] = ((const float4*)(Kbase + (size_t)(k0 + r) * EMBED))[c];
            ((float4*)Vs)[f] = ((const float4*)(Vbase + (size_t)(k0 + r) * EMBED))[c];
        }
        __syncthreads();

        for (int kk = 0; kk < KT; kk++) {
            const float4* krow = (const float4*)Ks[kk];
            float s0 = 0.f, s1 = 0.f, s2 = 0.f, s3 = 0.f;
            #pragma unroll
            for (int i = 0; i < 16; i += 4) {
                s0 += dot4(q4[i + 0], krow[i + 0]);
                s1 += dot4(q4[i + 1], krow[i + 1]);
                s2 += dot4(q4[i + 2], krow[i + 2]);
                s3 += dot4(q4[i + 3], krow[i + 3]);
            }
            float s = ((s0 + s1) + (s2 + s3)) * scale;

            if (s > mval) {
                float corr = exp2f(mval - s);
                mval = s;
                l *= corr;
                #pragma unroll
                for (int i = 0; i < 16; i++) {
                    o4[i].x *= corr; o4[i].y *= corr;
                    o4[i].z *= corr; o4[i].w *= corr;
                }
            }
            float p = exp2f(s - mval);
            l += p;

            const float4* vrow = (const float4*)Vs[kk];
            #pragma unroll
            for (int i = 0; i < 16; i++) {
                float4 vv = vrow[i];
                o4[i].x = fmaf(p, vv.x, o4[i].x);
                o4[i].y = fmaf(p, vv.y, o4[i].y);
                o4[i].z = fmaf(p, vv.z, o4[i].z);
                o4[i].w = fmaf(p, vv.w, o4[i].w);
            }
        }
    }

    const float inv = 1.0f / l;
    float* orow = Out + ((size_t)(bb * SEQ + qi)) * EMBED + h * HDIM;
    #pragma unroll
    for (int i = 0; i < 16; i++) {
        float4 ov;
        ov.x = o4[i].x * inv; ov.y = o4[i].y * inv;
        ov.z = o4[i].z * inv; ov.w = o4[i].w * inv;
        ((float4*)orow)[i] = ov;
    }
}

// ---------------- launch ----------------------------------------------------
extern "C" void kernel_launch(void* const* d_in, const int* in_sizes, int n_in,
                              void* d_out, int out_size)
{
    const float* q  = (const float*)d_in[0];
    const float* k  = (const float*)d_in[1];
    const float* v  = (const float*)d_in[2];
    const float* Wq = (const float*)d_in[3];
    const float* bq = (const float*)d_in[4];
    const float* Wk = (const float*)d_in[5];
    const float* bk = (const float*)d_in[6];
    const float* Wv = (const float*)d_in[7];
    const float* bv = (const float*)d_in[8];
    const float* Wo = (const float*)d_in[9];
    const float* bo = (const float*)d_in[10];
    float* out = (float*)d_out;

    float *Qp, *Kp, *Vp, *Attn;
    cudaGetSymbolAddress((void**)&Qp,   g_Qp);
    cudaGetSymbolAddress((void**)&Kp,   g_Kp);
    cudaGetSymbolAddress((void**)&Vp,   g_Vp);
    cudaGetSymbolAddress((void**)&Attn, g_Attn);

    dim3 gemm_grid(EMBED / GBN, MROWS / GBM);   // (8, 32)
    gemm_tf32_bias<<<gemm_grid, 256>>>(q, Wq, bq, Qp, MROWS, EMBED, EMBED);
    gemm_tf32_bias<<<gemm_grid, 256>>>(k, Wk, bk, Kp, MROWS, EMBED, EMBED);
    gemm_tf32_bias<<<gemm_grid, 256>>>(v, Wv, bv, Vp, MROWS, EMBED, EMBED);

    dim3 attn_grid(SEQ / QB, HEADS, BATCH);     // (16, 16, 2)
    attn_kernel<<<attn_grid, QB>>>(Qp, Kp, Vp, Attn);

    gemm_tf32_bias<<<gemm_grid, 256>>>(Attn, Wo, bo, out, MROWS, EMBED, EMBED);
}

// round 3
// speedup vs baseline: 3.6102x; 2.8023x over previous
#include <cuda_runtime.h>
#include <cuda_bf16.h>
#include <math.h>
#include <stdint.h>

// Problem constants
#define BATCH 2
#define SEQ   2048
#define EMBED 1024
#define HEADS 16
#define HDIM  64
#define MROWS (BATCH * SEQ)   // 4096

// ---------------- scratch (device globals; no runtime allocation) ----------
__device__ float g_Qp[MROWS * EMBED];
__device__ float g_Kp[MROWS * EMBED];
__device__ float g_Vp[MROWS * EMBED];
__device__ float g_Attn[MROWS * EMBED];

// ---------------- helpers ---------------------------------------------------
__device__ __forceinline__ uint32_t f2tf32(float x) {
    uint32_t r;
    asm("cvt.rna.tf32.f32 %0, %1;" : "=r"(r) : "f"(x));
    return r;
}

__device__ __forceinline__ float ex2(float x) {
    float r;
    asm("ex2.approx.f32 %0, %1;" : "=f"(r) : "f"(x));
    return r;
}

__device__ __forceinline__ void cp_async16(void* smem_ptr, const void* gmem_ptr) {
    uint32_t s = (uint32_t)__cvta_generic_to_shared(smem_ptr);
    asm volatile("cp.async.cg.shared.global [%0], [%1], 16;\n" :: "r"(s), "l"(gmem_ptr));
}
#define CP_ASYNC_COMMIT() asm volatile("cp.async.commit_group;\n" ::: "memory")
#define CP_ASYNC_WAIT0()  asm volatile("cp.async.wait_group 0;\n" ::: "memory")
#define CP_ASYNC_WAIT1()  asm volatile("cp.async.wait_group 1;\n" ::: "memory")

__device__ __forceinline__ void mma_tf32(float& d0, float& d1, float& d2, float& d3,
                                         uint32_t a0, uint32_t a1, uint32_t a2, uint32_t a3,
                                         uint32_t b0, uint32_t b1) {
    asm volatile(
        "mma.sync.aligned.m16n8k8.row.col.f32.tf32.tf32.f32 "
        "{%0,%1,%2,%3}, {%4,%5,%6,%7}, {%8,%9}, {%0,%1,%2,%3};\n"
        : "+f"(d0), "+f"(d1), "+f"(d2), "+f"(d3)
        : "r"(a0), "r"(a1), "r"(a2), "r"(a3), "r"(b0), "r"(b1));
}

// ---------------- TF32 tensor-core GEMM: C = A[M,K] @ B[K,N] + bias[N] -----
#define GBM 128
#define GBN 128
#define GBK 16
#define A_STRIDE (GBK + 4)
#define B_STRIDE (GBN + 8)

__global__ __launch_bounds__(256, 2)
void gemm_tf32_bias(const float* __restrict__ A,
                    const float* __restrict__ B,
                    const float* __restrict__ bias,
                    float* __restrict__ C,
                    int M, int N, int K)
{
    __shared__ float As[2][GBM * A_STRIDE];
    __shared__ float Bs[2][GBK * B_STRIDE];

    const int tid  = threadIdx.x;
    const int wid  = tid >> 5;
    const int lane = tid & 31;
    const int gi   = lane >> 2;
    const int ti   = lane & 3;

    const int brow = blockIdx.y;
    const int bcol = blockIdx.x;
    const int warp_m = (wid & 1) * 64;
    const int warp_n = (wid >> 1) * 32;

    const float* Ablk = A + (size_t)brow * GBM * K;
    const float* Bblk = B + (size_t)bcol * GBN;

    float acc[4][4][4];
    #pragma unroll
    for (int i = 0; i < 4; i++)
        #pragma unroll
        for (int j = 0; j < 4; j++)
            #pragma unroll
            for (int r = 0; r < 4; r++) acc[i][j][r] = 0.0f;

    const int NIT = K / GBK;

    auto load_tile = [&](int buf, int k0) {
        #pragma unroll
        for (int i = 0; i < 2; i++) {
            int f  = tid + i * 256;
            int r  = f >> 2;
            int c4 = f & 3;
            cp_async16(&As[buf][r * A_STRIDE + c4 * 4],
                       Ablk + (size_t)r * K + k0 + c4 * 4);
        }
        #pragma unroll
        for (int i = 0; i < 2; i++) {
            int f  = tid + i * 256;
            int r  = f >> 5;
            int c4 = f & 31;
            cp_async16(&Bs[buf][r * B_STRIDE + c4 * 4],
                       Bblk + (size_t)(k0 + r) * N + c4 * 4);
        }
        CP_ASYNC_COMMIT();
    };

    load_tile(0, 0);

    int buf = 0;
    for (int it = 0; it < NIT; it++) {
        CP_ASYNC_WAIT0();
        __syncthreads();
        if (it + 1 < NIT) load_tile(buf ^ 1, (it + 1) * GBK);

        const float* Asb = As[buf];
        const float* Bsb = Bs[buf];
        #pragma unroll
        for (int ks = 0; ks < GBK; ks += 8) {
            uint32_t afr[4][4];
            #pragma unroll
            for (int mt = 0; mt < 4; mt++) {
                int row = warp_m + mt * 16 + gi;
                int col = ks + ti;
                afr[mt][0] = f2tf32(Asb[row * A_STRIDE + col]);
                afr[mt][1] = f2tf32(Asb[(row + 8) * A_STRIDE + col]);
                afr[mt][2] = f2tf32(Asb[row * A_STRIDE + col + 4]);
                afr[mt][3] = f2tf32(Asb[(row + 8) * A_STRIDE + col + 4]);
            }
            uint32_t bfr[4][2];
            #pragma unroll
            for (int nt = 0; nt < 4; nt++) {
                int coln = warp_n + nt * 8 + gi;
                int rowk = ks + ti;
                bfr[nt][0] = f2tf32(Bsb[rowk * B_STRIDE + coln]);
                bfr[nt][1] = f2tf32(Bsb[(rowk + 4) * B_STRIDE + coln]);
            }
            #pragma unroll
            for (int mt = 0; mt < 4; mt++)
                #pragma unroll
                for (int nt = 0; nt < 4; nt++)
                    mma_tf32(acc[mt][nt][0], acc[mt][nt][1],
                             acc[mt][nt][2], acc[mt][nt][3],
                             afr[mt][0], afr[mt][1], afr[mt][2], afr[mt][3],
                             bfr[nt][0], bfr[nt][1]);
        }
        buf ^= 1;
        __syncthreads();
    }

    #pragma unroll
    for (int mt = 0; mt < 4; mt++) {
        int row0 = brow * GBM + warp_m + mt * 16 + gi;
        #pragma unroll
        for (int nt = 0; nt < 4; nt++) {
            int col0 = bcol * GBN + warp_n + nt * 8 + 2 * ti;
            float b0 = bias[col0], b1 = bias[col0 + 1];
            float2 v0 = make_float2(acc[mt][nt][0] + b0, acc[mt][nt][1] + b1);
            float2 v1 = make_float2(acc[mt][nt][2] + b0, acc[mt][nt][3] + b1);
            *(float2*)(C + (size_t)row0 * N + col0) = v0;
            *(float2*)(C + (size_t)(row0 + 8) * N + col0) = v1;
        }
    }
}

// ---------------- TF32 tensor-core flash attention -------------------------
// 8 warps / block; 128 Q rows per block (16 per warp); 64-key KV tiles,
// double-buffered cp.async. S = Q K^T and O += P V via m16n8k8 TF32 MMA.
#define KS_STRIDE 68
#define VS_STRIDE 72
#define PS_STRIDE 68
#define KS_TILE (64 * KS_STRIDE)
#define VS_TILE (64 * VS_STRIDE)
#define ATTN_SMEM_WORDS (2 * KS_TILE + 2 * VS_TILE + 128 * PS_STRIDE)
#define ATTN_SMEM_BYTES (ATTN_SMEM_WORDS * 4)

__global__ __launch_bounds__(256)
void attn_mma_kernel(const float* __restrict__ Qp,
                     const float* __restrict__ Kp,
                     const float* __restrict__ Vp,
                     float* __restrict__ Out)
{
    extern __shared__ float sm[];
    float* KsBuf = sm;                          // 2 x [64][KS_STRIDE]
    float* VsBuf = sm + 2 * KS_TILE;            // 2 x [64][VS_STRIDE]
    float* Pb    = sm + 2 * KS_TILE + 2 * VS_TILE;  // [128][PS_STRIDE]

    const int tid  = threadIdx.x;
    const int wid  = tid >> 5;
    const int lane = tid & 31;
    const int gi   = lane >> 2;   // 0..7
    const int ti   = lane & 3;    // 0..3
    const int h    = blockIdx.y;
    const int bb   = blockIdx.z;
    const int q0   = blockIdx.x * 128;

    const float* Qbase = Qp + ((size_t)(bb * SEQ + q0)) * EMBED + h * HDIM;
    const float* Kbase = Kp + ((size_t)bb * SEQ) * EMBED + h * HDIM;
    const float* Vbase = Vp + ((size_t)bb * SEQ) * EMBED + h * HDIM;

    // ---- stage Q tile [128 x 64] into Pb, then load per-warp a-frags ------
    #pragma unroll
    for (int i = 0; i < 8; i++) {
        int f = tid + i * 256;        // 0..2047
        int r = f >> 4, c4 = f & 15;
        cp_async16(&Pb[r * PS_STRIDE + c4 * 4], Qbase + (size_t)r * EMBED + c4 * 4);
    }
    CP_ASYNC_COMMIT();
    CP_ASYNC_WAIT0();
    __syncthreads();

    const float qscale = 0.125f * 1.4426950408889634f;  // 1/sqrt(64) * log2(e)
    uint32_t qf[8][4];
    {
        const float* Pw = Pb + (wid * 16) * PS_STRIDE;
        #pragma unroll
        for (int ks = 0; ks < 8; ks++) {
            qf[ks][0] = f2tf32(Pw[gi * PS_STRIDE + ks * 8 + ti] * qscale);
            qf[ks][1] = f2tf32(Pw[(gi + 8) * PS_STRIDE + ks * 8 + ti] * qscale);
            qf[ks][2] = f2tf32(Pw[gi * PS_STRIDE + ks * 8 + ti + 4] * qscale);
            qf[ks][3] = f2tf32(Pw[(gi + 8) * PS_STRIDE + ks * 8 + ti + 4] * qscale);
        }
    }
    __syncthreads();   // Pb now free for P round-trips

    float oacc[8][4];
    #pragma unroll
    for (int nt = 0; nt < 8; nt++)
        #pragma unroll
        for (int r = 0; r < 4; r++) oacc[nt][r] = 0.0f;
    float mA = -1e30f, mB = -1e30f, lA = 0.0f, lB = 0.0f;

    auto load_kv = [&](int t, int b) {
        const float* Kt = Kbase + (size_t)(t * 64) * EMBED;
        const float* Vt = Vbase + (size_t)(t * 64) * EMBED;
        float* Kd = KsBuf + b * KS_TILE;
        float* Vd = VsBuf + b * VS_TILE;
        #pragma unroll
        for (int i = 0; i < 4; i++) {
            int f = tid + i * 256;    // 0..1023
            int r = f >> 4, c4 = f & 15;
            cp_async16(&Kd[r * KS_STRIDE + c4 * 4], Kt + (size_t)r * EMBED + c4 * 4);
            cp_async16(&Vd[r * VS_STRIDE + c4 * 4], Vt + (size_t)r * EMBED + c4 * 4);
        }
        CP_ASYNC_COMMIT();
    };

    const int NT = SEQ / 64;
    load_kv(0, 0);
    int buf = 0;

    for (int t = 0; t < NT; t++) {
        if (t + 1 < NT) {
            load_kv(t + 1, buf ^ 1);
            CP_ASYNC_WAIT1();      // current tile's group done
        } else {
            CP_ASYNC_WAIT0();
        }
        __syncthreads();

        const float* Kd = KsBuf + buf * KS_TILE;
        const float* Vd = VsBuf + buf * VS_TILE;
        float* Pw = Pb + (wid * 16) * PS_STRIDE;

        // ---- S = Q K^T (scale folded into Q) ----
        float s[8][4];
        #pragma unroll
        for (int nt = 0; nt < 8; nt++) {
            s[nt][0] = s[nt][1] = s[nt][2] = s[nt][3] = 0.0f;
            #pragma unroll
            for (int ks = 0; ks < 8; ks++) {
                uint32_t b0 = f2tf32(Kd[(nt * 8 + gi) * KS_STRIDE + ks * 8 + ti]);
                uint32_t b1 = f2tf32(Kd[(nt * 8 + gi) * KS_STRIDE + ks * 8 + ti + 4]);
                mma_tf32(s[nt][0], s[nt][1], s[nt][2], s[nt][3],
                         qf[ks][0], qf[ks][1], qf[ks][2], qf[ks][3], b0, b1);
            }
        }

        // ---- online softmax (rows gi and gi+8) ----
        float mAt = -1e30f, mBt = -1e30f;
        #pragma unroll
        for (int nt = 0; nt < 8; nt++) {
            mAt = fmaxf(mAt, fmaxf(s[nt][0], s[nt][1]));
            mBt = fmaxf(mBt, fmaxf(s[nt][2], s[nt][3]));
        }
        mAt = fmaxf(mAt, __shfl_xor_sync(0xffffffffu, mAt, 1));
        mAt = fmaxf(mAt, __shfl_xor_sync(0xffffffffu, mAt, 2));
        mBt = fmaxf(mBt, __shfl_xor_sync(0xffffffffu, mBt, 1));
        mBt = fmaxf(mBt, __shfl_xor_sync(0xffffffffu, mBt, 2));

        float mA_new = fmaxf(mA, mAt), mB_new = fmaxf(mB, mBt);
        float cA = ex2(mA - mA_new), cB = ex2(mB - mB_new);

        float sA = 0.0f, sB = 0.0f;
        #pragma unroll
        for (int nt = 0; nt < 8; nt++) {
            float p0 = ex2(s[nt][0] - mA_new);
            float p1 = ex2(s[nt][1] - mA_new);
            float p2 = ex2(s[nt][2] - mB_new);
            float p3 = ex2(s[nt][3] - mB_new);
            sA += p0 + p1; sB += p2 + p3;
            uint2 uA = make_uint2(f2tf32(p0), f2tf32(p1));
            uint2 uB = make_uint2(f2tf32(p2), f2tf32(p3));
            *(uint2*)&Pw[gi * PS_STRIDE + nt * 8 + 2 * ti]       = uA;
            *(uint2*)&Pw[(gi + 8) * PS_STRIDE + nt * 8 + 2 * ti] = uB;
        }
        sA += __shfl_xor_sync(0xffffffffu, sA, 1);
        sA += __shfl_xor_sync(0xffffffffu, sA, 2);
        sB += __shfl_xor_sync(0xffffffffu, sB, 1);
        sB += __shfl_xor_sync(0xffffffffu, sB, 2);

        lA = lA * cA + sA;
        lB = lB * cB + sB;
        mA = mA_new; mB = mB_new;

        #pragma unroll
        for (int nt = 0; nt < 8; nt++) {
            oacc[nt][0] *= cA; oacc[nt][1] *= cA;
            oacc[nt][2] *= cB; oacc[nt][3] *= cB;
        }
        __syncwarp();

        // ---- O += P V ----
        #pragma unroll
        for (int nt = 0; nt < 8; nt++) {      // output dim tiles (n)
            #pragma unroll
            for (int ks = 0; ks < 8; ks++) {  // key chunks (k)
                uint32_t a0 = *(const uint32_t*)&Pw[gi * PS_STRIDE + ks * 8 + ti];
                uint32_t a1 = *(const uint32_t*)&Pw[(gi + 8) * PS_STRIDE + ks * 8 + ti];
                uint32_t a2 = *(const uint32_t*)&Pw[gi * PS_STRIDE + ks * 8 + ti + 4];
                uint32_t a3 = *(const uint32_t*)&Pw[(gi + 8) * PS_STRIDE + ks * 8 + ti + 4];
                uint32_t b0 = f2tf32(Vd[(ks * 8 + ti) * VS_STRIDE + nt * 8 + gi]);
                uint32_t b1 = f2tf32(Vd[(ks * 8 + ti + 4) * VS_STRIDE + nt * 8 + gi]);
                mma_tf32(oacc[nt][0], oacc[nt][1], oacc[nt][2], oacc[nt][3],
                         a0, a1, a2, a3, b0, b1);
            }
        }
        __syncthreads();   // all warps done with Kd/Vd before next prefetch overwrites
        buf ^= 1;
    }

    // ---- epilogue ----
    const float invA = 1.0f / lA, invB = 1.0f / lB;
    const int row0 = q0 + wid * 16 + gi;
    float* Ob = Out + ((size_t)(bb * SEQ + row0)) * EMBED + h * HDIM;
    #pragma unroll
    for (int nt = 0; nt < 8; nt++) {
        int col = nt * 8 + 2 * ti;
        float2 vA = make_float2(oacc[nt][0] * invA, oacc[nt][1] * invA);
        float2 vB = make_float2(oacc[nt][2] * invB, oacc[nt][3] * invB);
        *(float2*)(Ob + col) = vA;
        *(float2*)(Ob + (size_t)8 * EMBED + col) = vB;
    }
}

// ---------------- launch ----------------------------------------------------
extern "C" void kernel_launch(void* const* d_in, const int* in_sizes, int n_in,
                              void* d_out, int out_size)
{
    const float* q  = (const float*)d_in[0];
    const float* k  = (const float*)d_in[1];
    const float* v  = (const float*)d_in[2];
    const float* Wq = (const float*)d_in[3];
    const float* bq = (const float*)d_in[4];
    const float* Wk = (const float*)d_in[5];
    const float* bk = (const float*)d_in[6];
    const float* Wv = (const float*)d_in[7];
    const float* bv = (const float*)d_in[8];
    const float* Wo = (const float*)d_in[9];
    const float* bo = (const float*)d_in[10];
    float* out = (float*)d_out;

    float *Qp, *Kp, *Vp, *Attn;
    cudaGetSymbolAddress((void**)&Qp,   g_Qp);
    cudaGetSymbolAddress((void**)&Kp,   g_Kp);
    cudaGetSymbolAddress((void**)&Vp,   g_Vp);
    cudaGetSymbolAddress((void**)&Attn, g_Attn);

    static bool attr_set = false;
    if (!attr_set) {
        cudaFuncSetAttribute(attn_mma_kernel,
                             cudaFuncAttributeMaxDynamicSharedMemorySize,
                             ATTN_SMEM_BYTES);
        attr_set = true;
    }

    dim3 gemm_grid(EMBED / GBN, MROWS / GBM);   // (8, 32)
    gemm_tf32_bias<<<gemm_grid, 256>>>(q, Wq, bq, Qp, MROWS, EMBED, EMBED);
    gemm_tf32_bias<<<gemm_grid, 256>>>(k, Wk, bk, Kp, MROWS, EMBED, EMBED);
    gemm_tf32_bias<<<gemm_grid, 256>>>(v, Wv, bv, Vp, MROWS, EMBED, EMBED);

    dim3 attn_grid(SEQ / 128, HEADS, BATCH);    // (16, 16, 2)
    attn_mma_kernel<<<attn_grid, 256, ATTN_SMEM_BYTES>>>(Qp, Kp, Vp, Attn);

    gemm_tf32_bias<<<gemm_grid, 256>>>(Attn, Wo, bo, out, MROWS, EMBED, EMBED);
}

// round 4
// speedup vs baseline: 4.0262x; 1.1152x over previous
#include <cuda_runtime.h>
#include <cuda_bf16.h>
#include <math.h>
#include <stdint.h>

// Problem constants
#define BATCH 2
#define SEQ   2048
#define EMBED 1024
#define HEADS 16
#define HDIM  64
#define MROWS (BATCH * SEQ)   // 4096

// ---------------- scratch (device globals; no runtime allocation) ----------
__device__ float g_Qp[MROWS * EMBED];
__device__ float g_Kp[MROWS * EMBED];
__device__ float g_Vp[MROWS * EMBED];
__device__ float g_Attn[MROWS * EMBED];
// pre-rounded (TF32/RNA) copies of inputs and weights
__device__ float g_qr[MROWS * EMBED];
__device__ float g_kr[MROWS * EMBED];
__device__ float g_vr[MROWS * EMBED];
__device__ float g_Wqr[EMBED * EMBED];
__device__ float g_Wkr[EMBED * EMBED];
__device__ float g_Wvr[EMBED * EMBED];
__device__ float g_Wor[EMBED * EMBED];

// ---------------- helpers ---------------------------------------------------
__device__ __forceinline__ uint32_t f2tf32(float x) {
    uint32_t r;
    asm("cvt.rna.tf32.f32 %0, %1;" : "=r"(r) : "f"(x));
    return r;
}

__device__ __forceinline__ float ex2(float x) {
    float r;
    asm("ex2.approx.f32 %0, %1;" : "=f"(r) : "f"(x));
    return r;
}

__device__ __forceinline__ void cp_async16(void* smem_ptr, const void* gmem_ptr) {
    uint32_t s = (uint32_t)__cvta_generic_to_shared(smem_ptr);
    asm volatile("cp.async.cg.shared.global [%0], [%1], 16;\n" :: "r"(s), "l"(gmem_ptr));
}
#define CP_ASYNC_COMMIT() asm volatile("cp.async.commit_group;\n" ::: "memory")
#define CP_ASYNC_WAIT0()  asm volatile("cp.async.wait_group 0;\n" ::: "memory")
#define CP_ASYNC_WAIT1()  asm volatile("cp.async.wait_group 1;\n" ::: "memory")

__device__ __forceinline__ void mma_tf32(float& d0, float& d1, float& d2, float& d3,
                                         uint32_t a0, uint32_t a1, uint32_t a2, uint32_t a3,
                                         uint32_t b0, uint32_t b1) {
    asm volatile(
        "mma.sync.aligned.m16n8k8.row.col.f32.tf32.tf32.f32 "
        "{%0,%1,%2,%3}, {%4,%5,%6,%7}, {%8,%9}, {%0,%1,%2,%3};\n"
        : "+f"(d0), "+f"(d1), "+f"(d2), "+f"(d3)
        : "r"(a0), "r"(a1), "r"(a2), "r"(a3), "r"(b0), "r"(b1));
}

// ---------------- TF32 pre-rounding pass ------------------------------------
__global__ __launch_bounds__(256)
void round_tf32_vec(const float4* __restrict__ in, float4* __restrict__ out, int n4)
{
    int i = blockIdx.x * blockDim.x + threadIdx.x;
    if (i < n4) {
        float4 v = in[i];
        v.x = __uint_as_float(f2tf32(v.x));
        v.y = __uint_as_float(f2tf32(v.y));
        v.z = __uint_as_float(f2tf32(v.z));
        v.w = __uint_as_float(f2tf32(v.w));
        out[i] = v;
    }
}

// ---------------- TF32 tensor-core GEMM: C = A[M,K] @ B[K,N] + bias[N] -----
// A and B must already be TF32-rounded. If ROUND_C, output is rounded too.
#define GBM 128
#define GBN 128
#define GBK 16
#define A_STRIDE (GBK + 4)
#define B_STRIDE (GBN + 8)

template<bool ROUND_C>
__global__ __launch_bounds__(256, 2)
void gemm_tf32_bias(const float* __restrict__ A,
                    const float* __restrict__ B,
                    const float* __restrict__ bias,
                    float* __restrict__ C,
                    int M, int N, int K)
{
    __shared__ float As[2][GBM * A_STRIDE];
    __shared__ float Bs[2][GBK * B_STRIDE];

    const int tid  = threadIdx.x;
    const int wid  = tid >> 5;
    const int lane = tid & 31;
    const int gi   = lane >> 2;
    const int ti   = lane & 3;

    const int brow = blockIdx.y;
    const int bcol = blockIdx.x;
    const int warp_m = (wid & 1) * 64;
    const int warp_n = (wid >> 1) * 32;

    const float* Ablk = A + (size_t)brow * GBM * K;
    const float* Bblk = B + (size_t)bcol * GBN;

    float acc[4][4][4];
    #pragma unroll
    for (int i = 0; i < 4; i++)
        #pragma unroll
        for (int j = 0; j < 4; j++)
            #pragma unroll
            for (int r = 0; r < 4; r++) acc[i][j][r] = 0.0f;

    const int NIT = K / GBK;

    auto load_tile = [&](int buf, int k0) {
        #pragma unroll
        for (int i = 0; i < 2; i++) {
            int f  = tid + i * 256;
            int r  = f >> 2;
            int c4 = f & 3;
            cp_async16(&As[buf][r * A_STRIDE + c4 * 4],
                       Ablk + (size_t)r * K + k0 + c4 * 4);
        }
        #pragma unroll
        for (int i = 0; i < 2; i++) {
            int f  = tid + i * 256;
            int r  = f >> 5;
            int c4 = f & 31;
            cp_async16(&Bs[buf][r * B_STRIDE + c4 * 4],
                       Bblk + (size_t)(k0 + r) * N + c4 * 4);
        }
        CP_ASYNC_COMMIT();
    };

    load_tile(0, 0);

    int buf = 0;
    for (int it = 0; it < NIT; it++) {
        CP_ASYNC_WAIT0();
        __syncthreads();
        if (it + 1 < NIT) load_tile(buf ^ 1, (it + 1) * GBK);

        const float* Asb = As[buf];
        const float* Bsb = Bs[buf];
        #pragma unroll
        for (int ks = 0; ks < GBK; ks += 8) {
            uint32_t afr[4][4];
            #pragma unroll
            for (int mt = 0; mt < 4; mt++) {
                int row = warp_m + mt * 16 + gi;
                int col = ks + ti;
                afr[mt][0] = __float_as_uint(Asb[row * A_STRIDE + col]);
                afr[mt][1] = __float_as_uint(Asb[(row + 8) * A_STRIDE + col]);
                afr[mt][2] = __float_as_uint(Asb[row * A_STRIDE + col + 4]);
                afr[mt][3] = __float_as_uint(Asb[(row + 8) * A_STRIDE + col + 4]);
            }
            uint32_t bfr[4][2];
            #pragma unroll
            for (int nt = 0; nt < 4; nt++) {
                int coln = warp_n + nt * 8 + gi;
                int rowk = ks + ti;
                bfr[nt][0] = __float_as_uint(Bsb[rowk * B_STRIDE + coln]);
                bfr[nt][1] = __float_as_uint(Bsb[(rowk + 4) * B_STRIDE + coln]);
            }
            #pragma unroll
            for (int mt = 0; mt < 4; mt++)
                #pragma unroll
                for (int nt = 0; nt < 4; nt++)
                    mma_tf32(acc[mt][nt][0], acc[mt][nt][1],
                             acc[mt][nt][2], acc[mt][nt][3],
                             afr[mt][0], afr[mt][1], afr[mt][2], afr[mt][3],
                             bfr[nt][0], bfr[nt][1]);
        }
        buf ^= 1;
        __syncthreads();
    }

    #pragma unroll
    for (int mt = 0; mt < 4; mt++) {
        int row0 = brow * GBM + warp_m + mt * 16 + gi;
        #pragma unroll
        for (int nt = 0; nt < 4; nt++) {
            int col0 = bcol * GBN + warp_n + nt * 8 + 2 * ti;
            float b0 = bias[col0], b1 = bias[col0 + 1];
            float c00 = acc[mt][nt][0] + b0, c01 = acc[mt][nt][1] + b1;
            float c10 = acc[mt][nt][2] + b0, c11 = acc[mt][nt][3] + b1;
            if (ROUND_C) {
                c00 = __uint_as_float(f2tf32(c00));
                c01 = __uint_as_float(f2tf32(c01));
                c10 = __uint_as_float(f2tf32(c10));
                c11 = __uint_as_float(f2tf32(c11));
            }
            *(float2*)(C + (size_t)row0 * N + col0)       = make_float2(c00, c01);
            *(float2*)(C + (size_t)(row0 + 8) * N + col0) = make_float2(c10, c11);
        }
    }
}

// ---------------- TF32 tensor-core flash attention -------------------------
// Inputs Qp/Kp/Vp are pre-rounded TF32 values stored as float.
#define KS_STRIDE 68
#define VS_STRIDE 72
#define PS_STRIDE 68
#define KS_TILE (64 * KS_STRIDE)
#define VS_TILE (64 * VS_STRIDE)
#define ATTN_SMEM_WORDS (2 * KS_TILE + 2 * VS_TILE + 128 * PS_STRIDE)
#define ATTN_SMEM_BYTES (ATTN_SMEM_WORDS * 4)

__global__ __launch_bounds__(256, 2)
void attn_mma_kernel(const float* __restrict__ Qp,
                     const float* __restrict__ Kp,
                     const float* __restrict__ Vp,
                     float* __restrict__ Out)
{
    extern __shared__ float sm[];
    float* KsBuf = sm;
    float* VsBuf = sm + 2 * KS_TILE;
    float* Pb    = sm + 2 * KS_TILE + 2 * VS_TILE;

    const int tid  = threadIdx.x;
    const int wid  = tid >> 5;
    const int lane = tid & 31;
    const int gi   = lane >> 2;
    const int ti   = lane & 3;
    const int h    = blockIdx.y;
    const int bb   = blockIdx.z;
    const int q0   = blockIdx.x * 128;

    const float* Qbase = Qp + ((size_t)(bb * SEQ + q0)) * EMBED + h * HDIM;
    const float* Kbase = Kp + ((size_t)bb * SEQ) * EMBED + h * HDIM;
    const float* Vbase = Vp + ((size_t)bb * SEQ) * EMBED + h * HDIM;

    // ---- stage Q tile [128 x 64] into Pb, build scaled TF32 a-frags --------
    #pragma unroll
    for (int i = 0; i < 8; i++) {
        int f = tid + i * 256;
        int r = f >> 4, c4 = f & 15;
        cp_async16(&Pb[r * PS_STRIDE + c4 * 4], Qbase + (size_t)r * EMBED + c4 * 4);
    }
    CP_ASYNC_COMMIT();
    CP_ASYNC_WAIT0();
    __syncthreads();

    const float qscale = 0.125f * 1.4426950408889634f;  // 1/sqrt(64) * log2(e)
    uint32_t qf[8][4];
    {
        const float* Pw = Pb + (wid * 16) * PS_STRIDE;
        #pragma unroll
        for (int ks = 0; ks < 8; ks++) {
            qf[ks][0] = f2tf32(Pw[gi * PS_STRIDE + ks * 8 + ti] * qscale);
            qf[ks][1] = f2tf32(Pw[(gi + 8) * PS_STRIDE + ks * 8 + ti] * qscale);
            qf[ks][2] = f2tf32(Pw[gi * PS_STRIDE + ks * 8 + ti + 4] * qscale);
            qf[ks][3] = f2tf32(Pw[(gi + 8) * PS_STRIDE + ks * 8 + ti + 4] * qscale);
        }
    }
    __syncthreads();

    float oacc[8][4];
    #pragma unroll
    for (int nt = 0; nt < 8; nt++)
        #pragma unroll
        for (int r = 0; r < 4; r++) oacc[nt][r] = 0.0f;
    float mA = -1e30f, mB = -1e30f, lA = 0.0f, lB = 0.0f;

    auto load_kv = [&](int t, int b) {
        const float* Kt = Kbase + (size_t)(t * 64) * EMBED;
        const float* Vt = Vbase + (size_t)(t * 64) * EMBED;
        float* Kd = KsBuf + b * KS_TILE;
        float* Vd = VsBuf + b * VS_TILE;
        #pragma unroll
        for (int i = 0; i < 4; i++) {
            int f = tid + i * 256;
            int r = f >> 4, c4 = f & 15;
            cp_async16(&Kd[r * KS_STRIDE + c4 * 4], Kt + (size_t)r * EMBED + c4 * 4);
            cp_async16(&Vd[r * VS_STRIDE + c4 * 4], Vt + (size_t)r * EMBED + c4 * 4);
        }
        CP_ASYNC_COMMIT();
    };

    const int NT = SEQ / 64;
    load_kv(0, 0);
    int buf = 0;

    for (int t = 0; t < NT; t++) {
        if (t + 1 < NT) {
            load_kv(t + 1, buf ^ 1);
            CP_ASYNC_WAIT1();
        } else {
            CP_ASYNC_WAIT0();
        }
        __syncthreads();

        const float* Kd = KsBuf + buf * KS_TILE;
        const float* Vd = VsBuf + buf * VS_TILE;
        float* Pw = Pb + (wid * 16) * PS_STRIDE;

        // ---- S = Q K^T (K already TF32-rounded; raw bit loads) ----
        float s[8][4];
        #pragma unroll
        for (int nt = 0; nt < 8; nt++) {
            s[nt][0] = s[nt][1] = s[nt][2] = s[nt][3] = 0.0f;
            #pragma unroll
            for (int ks = 0; ks < 8; ks++) {
                uint32_t b0 = __float_as_uint(Kd[(nt * 8 + gi) * KS_STRIDE + ks * 8 + ti]);
                uint32_t b1 = __float_as_uint(Kd[(nt * 8 + gi) * KS_STRIDE + ks * 8 + ti + 4]);
                mma_tf32(s[nt][0], s[nt][1], s[nt][2], s[nt][3],
                         qf[ks][0], qf[ks][1], qf[ks][2], qf[ks][3], b0, b1);
            }
        }

        // ---- online softmax (rows gi and gi+8) ----
        float mAt = -1e30f, mBt = -1e30f;
        #pragma unroll
        for (int nt = 0; nt < 8; nt++) {
            mAt = fmaxf(mAt, fmaxf(s[nt][0], s[nt][1]));
            mBt = fmaxf(mBt, fmaxf(s[nt][2], s[nt][3]));
        }
        mAt = fmaxf(mAt, __shfl_xor_sync(0xffffffffu, mAt, 1));
        mAt = fmaxf(mAt, __shfl_xor_sync(0xffffffffu, mAt, 2));
        mBt = fmaxf(mBt, __shfl_xor_sync(0xffffffffu, mBt, 1));
        mBt = fmaxf(mBt, __shfl_xor_sync(0xffffffffu, mBt, 2));

        float mA_new = fmaxf(mA, mAt), mB_new = fmaxf(mB, mBt);
        float cA = ex2(mA - mA_new), cB = ex2(mB - mB_new);

        float sA = 0.0f, sB = 0.0f;
        #pragma unroll
        for (int nt = 0; nt < 8; nt++) {
            float p0 = ex2(s[nt][0] - mA_new);
            float p1 = ex2(s[nt][1] - mA_new);
            float p2 = ex2(s[nt][2] - mB_new);
            float p3 = ex2(s[nt][3] - mB_new);
            sA += p0 + p1; sB += p2 + p3;
            uint2 uA = make_uint2(f2tf32(p0), f2tf32(p1));
            uint2 uB = make_uint2(f2tf32(p2), f2tf32(p3));
            *(uint2*)&Pw[gi * PS_STRIDE + nt * 8 + 2 * ti]       = uA;
            *(uint2*)&Pw[(gi + 8) * PS_STRIDE + nt * 8 + 2 * ti] = uB;
        }
        sA += __shfl_xor_sync(0xffffffffu, sA, 1);
        sA += __shfl_xor_sync(0xffffffffu, sA, 2);
        sB += __shfl_xor_sync(0xffffffffu, sB, 1);
        sB += __shfl_xor_sync(0xffffffffu, sB, 2);

        lA = lA * cA + sA;
        lB = lB * cB + sB;
        mA = mA_new; mB = mB_new;

        #pragma unroll
        for (int nt = 0; nt < 8; nt++) {
            oacc[nt][0] *= cA; oacc[nt][1] *= cA;
            oacc[nt][2] *= cB; oacc[nt][3] *= cB;
        }
        __syncwarp();

        // ---- O += P V (a-frags depend only on ks: hoisted) ----
        #pragma unroll
        for (int ks = 0; ks < 8; ks++) {
            uint32_t a0 = *(const uint32_t*)&Pw[gi * PS_STRIDE + ks * 8 + ti];
            uint32_t a1 = *(const uint32_t*)&Pw[(gi + 8) * PS_STRIDE + ks * 8 + ti];
            uint32_t a2 = *(const uint32_t*)&Pw[gi * PS_STRIDE + ks * 8 + ti + 4];
            uint32_t a3 = *(const uint32_t*)&Pw[(gi + 8) * PS_STRIDE + ks * 8 + ti + 4];
            #pragma unroll
            for (int nt = 0; nt < 8; nt++) {
                uint32_t b0 = __float_as_uint(Vd[(ks * 8 + ti) * VS_STRIDE + nt * 8 + gi]);
                uint32_t b1 = __float_as_uint(Vd[(ks * 8 + ti + 4) * VS_STRIDE + nt * 8 + gi]);
                mma_tf32(oacc[nt][0], oacc[nt][1], oacc[nt][2], oacc[nt][3],
                         a0, a1, a2, a3, b0, b1);
            }
        }
        __syncthreads();
        buf ^= 1;
    }

    // ---- epilogue: normalize + TF32-round (feeds O-projection directly) ----
    const float invA = 1.0f / lA, invB = 1.0f / lB;
    const int row0 = q0 + wid * 16 + gi;
    float* Ob = Out + ((size_t)(bb * SEQ + row0)) * EMBED + h * HDIM;
    #pragma unroll
    for (int nt = 0; nt < 8; nt++) {
        int col = nt * 8 + 2 * ti;
        float2 vA, vB;
        vA.x = __uint_as_float(f2tf32(oacc[nt][0] * invA));
        vA.y = __uint_as_float(f2tf32(oacc[nt][1] * invA));
        vB.x = __uint_as_float(f2tf32(oacc[nt][2] * invB));
        vB.y = __uint_as_float(f2tf32(oacc[nt][3] * invB));
        *(float2*)(Ob + col) = vA;
        *(float2*)(Ob + (size_t)8 * EMBED + col) = vB;
    }
}

// ---------------- launch ----------------------------------------------------
extern "C" void kernel_launch(void* const* d_in, const int* in_sizes, int n_in,
                              void* d_out, int out_size)
{
    const float* q  = (const float*)d_in[0];
    const float* k  = (const float*)d_in[1];
    const float* v  = (const float*)d_in[2];
    const float* Wq = (const float*)d_in[3];
    const float* bq = (const float*)d_in[4];
    const float* Wk = (const float*)d_in[5];
    const float* bk = (const float*)d_in[6];
    const float* Wv = (const float*)d_in[7];
    const float* bv = (const float*)d_in[8];
    const float* Wo = (const float*)d_in[9];
    const float* bo = (const float*)d_in[10];
    float* out = (float*)d_out;

    float *Qp, *Kp, *Vp, *Attn, *qr, *kr, *vr, *Wqr, *Wkr, *Wvr, *Wor;
    cudaGetSymbolAddress((void**)&Qp,   g_Qp);
    cudaGetSymbolAddress((void**)&Kp,   g_Kp);
    cudaGetSymbolAddress((void**)&Vp,   g_Vp);
    cudaGetSymbolAddress((void**)&Attn, g_Attn);
    cudaGetSymbolAddress((void**)&qr,   g_qr);
    cudaGetSymbolAddress((void**)&kr,   g_kr);
    cudaGetSymbolAddress((void**)&vr,   g_vr);
    cudaGetSymbolAddress((void**)&Wqr,  g_Wqr);
    cudaGetSymbolAddress((void**)&Wkr,  g_Wkr);
    cudaGetSymbolAddress((void**)&Wvr,  g_Wvr);
    cudaGetSymbolAddress((void**)&Wor,  g_Wor);

    cudaFuncSetAttribute(attn_mma_kernel,
                         cudaFuncAttributeMaxDynamicSharedMemorySize,
                         ATTN_SMEM_BYTES);

    // pre-round inputs and weights to TF32 (RNA)
    const int BIG4   = MROWS * EMBED / 4;      // 1,048,576 float4
    const int W4     = EMBED * EMBED / 4;      // 262,144 float4
    round_tf32_vec<<<BIG4 / 256, 256>>>((const float4*)q,  (float4*)qr,  BIG4);
    round_tf32_vec<<<BIG4 / 256, 256>>>((const float4*)k,  (float4*)kr,  BIG4);
    round_tf32_vec<<<BIG4 / 256, 256>>>((const float4*)v,  (float4*)vr,  BIG4);
    round_tf32_vec<<<W4 / 256,  256>>>((const float4*)Wq, (float4*)Wqr, W4);
    round_tf32_vec<<<W4 / 256,  256>>>((const float4*)Wk, (float4*)Wkr, W4);
    round_tf32_vec<<<W4 / 256,  256>>>((const float4*)Wv, (float4*)Wvr, W4);
    round_tf32_vec<<<W4 / 256,  256>>>((const float4*)Wo, (float4*)Wor, W4);

    dim3 gemm_grid(EMBED / GBN, MROWS / GBM);   // (8, 32)
    gemm_tf32_bias<true><<<gemm_grid, 256>>>(qr, Wqr, bq, Qp, MROWS, EMBED, EMBED);
    gemm_tf32_bias<true><<<gemm_grid, 256>>>(kr, Wkr, bk, Kp, MROWS, EMBED, EMBED);
    gemm_tf32_bias<true><<<gemm_grid, 256>>>(vr, Wvr, bv, Vp, MROWS, EMBED, EMBED);

    dim3 attn_grid(SEQ / 128, HEADS, BATCH);    // (16, 16, 2)
    attn_mma_kernel<<<attn_grid, 256, ATTN_SMEM_BYTES>>>(Qp, Kp, Vp, Attn);

    gemm_tf32_bias<false><<<gemm_grid, 256>>>(Attn, Wor, bo, out, MROWS, EMBED, EMBED);
}

// round 6
// speedup vs baseline: 4.5584x; 1.1322x over previous
#include <cuda_runtime.h>
#include <cuda_bf16.h>
#include <math.h>
#include <stdint.h>

// Problem constants
#define BATCH 2
#define SEQ   2048
#define EMBED 1024
#define HEADS 16
#define HDIM  64
#define MROWS (BATCH * SEQ)   // 4096

// ---------------- scratch (device globals; no runtime allocation) ----------
__device__ float g_Qp[MROWS * EMBED];
__device__ float g_Kp[MROWS * EMBED];
__device__ float g_Vp[MROWS * EMBED];
__device__ float g_Attn[MROWS * EMBED];
__device__ float g_qr[MROWS * EMBED];
__device__ float g_kr[MROWS * EMBED];
__device__ float g_vr[MROWS * EMBED];
__device__ float g_Wqr[EMBED * EMBED];
__device__ float g_Wkr[EMBED * EMBED];
__device__ float g_Wvr[EMBED * EMBED];
__device__ float g_Wor[EMBED * EMBED];

// ---------------- helpers ---------------------------------------------------
__device__ __forceinline__ uint32_t f2tf32(float x) {
    uint32_t r;
    asm("cvt.rna.tf32.f32 %0, %1;" : "=r"(r) : "f"(x));
    return r;
}

__device__ __forceinline__ float ex2(float x) {
    float r;
    asm("ex2.approx.f32 %0, %1;" : "=f"(r) : "f"(x));
    return r;
}

__device__ __forceinline__ void cp_async16(void* smem_ptr, const void* gmem_ptr) {
    uint32_t s = (uint32_t)__cvta_generic_to_shared(smem_ptr);
    asm volatile("cp.async.cg.shared.global [%0], [%1], 16;\n" :: "r"(s), "l"(gmem_ptr));
}
#define CP_ASYNC_COMMIT() asm volatile("cp.async.commit_group;\n" ::: "memory")
#define CP_ASYNC_WAIT0()  asm volatile("cp.async.wait_group 0;\n" ::: "memory")
#define CP_ASYNC_WAIT1()  asm volatile("cp.async.wait_group 1;\n" ::: "memory")

__device__ __forceinline__ void mma_tf32(float& d0, float& d1, float& d2, float& d3,
                                         uint32_t a0, uint32_t a1, uint32_t a2, uint32_t a3,
                                         uint32_t b0, uint32_t b1) {
    asm volatile(
        "mma.sync.aligned.m16n8k8.row.col.f32.tf32.tf32.f32 "
        "{%0,%1,%2,%3}, {%4,%5,%6,%7}, {%8,%9}, {%0,%1,%2,%3};\n"
        : "+f"(d0), "+f"(d1), "+f"(d2), "+f"(d3)
        : "r"(a0), "r"(a1), "r"(a2), "r"(a3), "r"(b0), "r"(b1));
}

// ---------------- TF32 pre-rounding pass ------------------------------------
__global__ __launch_bounds__(256)
void round_tf32_vec(const float4* __restrict__ in, float4* __restrict__ out, int n4)
{
    int i = blockIdx.x * blockDim.x + threadIdx.x;
    if (i < n4) {
        float4 v = in[i];
        v.x = __uint_as_float(f2tf32(v.x));
        v.y = __uint_as_float(f2tf32(v.y));
        v.z = __uint_as_float(f2tf32(v.z));
        v.w = __uint_as_float(f2tf32(v.w));
        out[i] = v;
    }
}

// ---------------- TF32 tensor-core GEMM: C = A[M,K] @ B[K,N] + bias[N] -----
// Block tile 128x128, 4 warps, warp tile 64x64, m16n8k8 MMAs, double buffer.
#define GBM 128
#define GBN 128
#define GBK 16
#define A_STRIDE (GBK + 4)   // 20
#define B_STRIDE (GBN + 8)   // 136

template<bool ROUND_C>
__global__ __launch_bounds__(128, 2)
void gemm_tf32_bias(const float* __restrict__ A,
                    const float* __restrict__ B,
                    const float* __restrict__ bias,
                    float* __restrict__ C,
                    int M, int N, int K)
{
    __shared__ float As[2][GBM * A_STRIDE];
    __shared__ float Bs[2][GBK * B_STRIDE];

    const int tid  = threadIdx.x;
    const int wid  = tid >> 5;          // 0..3
    const int lane = tid & 31;
    const int gi   = lane >> 2;
    const int ti   = lane & 3;

    const int brow = blockIdx.y;
    const int bcol = blockIdx.x;
    const int warp_m = (wid & 1) * 64;   // 0 or 64
    const int warp_n = (wid >> 1) * 64;  // 0 or 64

    const float* Ablk = A + (size_t)brow * GBM * K;
    const float* Bblk = B + (size_t)bcol * GBN;

    float acc[4][8][4];
    #pragma unroll
    for (int i = 0; i < 4; i++)
        #pragma unroll
        for (int j = 0; j < 8; j++)
            #pragma unroll
            for (int r = 0; r < 4; r++) acc[i][j][r] = 0.0f;

    const int NIT = K / GBK;

    auto load_tile = [&](int buf, int k0) {
        #pragma unroll
        for (int i = 0; i < 4; i++) {
            int f  = tid + i * 128;       // 0..511
            int r  = f >> 2;              // 0..127
            int c4 = f & 3;
            cp_async16(&As[buf][r * A_STRIDE + c4 * 4],
                       Ablk + (size_t)r * K + k0 + c4 * 4);
        }
        #pragma unroll
        for (int i = 0; i < 4; i++) {
            int f  = tid + i * 128;
            int r  = f >> 5;              // 0..15
            int c4 = f & 31;
            cp_async16(&Bs[buf][r * B_STRIDE + c4 * 4],
                       Bblk + (size_t)(k0 + r) * N + c4 * 4);
        }
        CP_ASYNC_COMMIT();
    };

    load_tile(0, 0);

    int buf = 0;
    for (int it = 0; it < NIT; it++) {
        CP_ASYNC_WAIT0();
        __syncthreads();
        if (it + 1 < NIT) load_tile(buf ^ 1, (it + 1) * GBK);

        const float* Asb = As[buf];
        const float* Bsb = Bs[buf];
        #pragma unroll
        for (int ks = 0; ks < GBK; ks += 8) {
            uint32_t afr[4][4];
            #pragma unroll
            for (int mt = 0; mt < 4; mt++) {
                int row = warp_m + mt * 16 + gi;
                int col = ks + ti;
                afr[mt][0] = __float_as_uint(Asb[row * A_STRIDE + col]);
                afr[mt][1] = __float_as_uint(Asb[(row + 8) * A_STRIDE + col]);
                afr[mt][2] = __float_as_uint(Asb[row * A_STRIDE + col + 4]);
                afr[mt][3] = __float_as_uint(Asb[(row + 8) * A_STRIDE + col + 4]);
            }
            uint32_t bfr[8][2];
            #pragma unroll
            for (int nt = 0; nt < 8; nt++) {
                int coln = warp_n + nt * 8 + gi;
                int rowk = ks + ti;
                bfr[nt][0] = __float_as_uint(Bsb[rowk * B_STRIDE + coln]);
                bfr[nt][1] = __float_as_uint(Bsb[(rowk + 4) * B_STRIDE + coln]);
            }
            #pragma unroll
            for (int mt = 0; mt < 4; mt++)
                #pragma unroll
                for (int nt = 0; nt < 8; nt++)
                    mma_tf32(acc[mt][nt][0], acc[mt][nt][1],
                             acc[mt][nt][2], acc[mt][nt][3],
                             afr[mt][0], afr[mt][1], afr[mt][2], afr[mt][3],
                             bfr[nt][0], bfr[nt][1]);
        }
        buf ^= 1;
        __syncthreads();
    }

    #pragma unroll
    for (int mt = 0; mt < 4; mt++) {
        int row0 = brow * GBM + warp_m + mt * 16 + gi;
        #pragma unroll
        for (int nt = 0; nt < 8; nt++) {
            int col0 = bcol * GBN + warp_n + nt * 8 + 2 * ti;
            float b0 = bias[col0], b1 = bias[col0 + 1];
            float c00 = acc[mt][nt][0] + b0, c01 = acc[mt][nt][1] + b1;
            float c10 = acc[mt][nt][2] + b0, c11 = acc[mt][nt][3] + b1;
            if (ROUND_C) {
                c00 = __uint_as_float(f2tf32(c00));
                c01 = __uint_as_float(f2tf32(c01));
                c10 = __uint_as_float(f2tf32(c10));
                c11 = __uint_as_float(f2tf32(c11));
            }
            *(float2*)(C + (size_t)row0 * N + col0)       = make_float2(c00, c01);
            *(float2*)(C + (size_t)(row0 + 8) * N + col0) = make_float2(c10, c11);
        }
    }
}

// ---------------- TF32 mma.sync flash attention -----------------------------
// 4 warps / 128 threads; each warp owns 32 Q rows (two 16-row m-tiles) so
// every K/V b-fragment is reused across two MMAs. 64-key KV tiles, double
// buffered cp.async; P round-trips through SMEM.
#define KS_STRIDE 68
#define VS_STRIDE 72
#define PS_STRIDE 68
#define KS_TILE (64 * KS_STRIDE)
#define VS_TILE (64 * VS_STRIDE)
#define ATTN_SMEM_WORDS (2 * KS_TILE + 2 * VS_TILE + 128 * PS_STRIDE)
#define ATTN_SMEM_BYTES (ATTN_SMEM_WORDS * 4)

__global__ __launch_bounds__(128, 2)
void attn_mma_kernel(const float* __restrict__ Qp,
                     const float* __restrict__ Kp,
                     const float* __restrict__ Vp,
                     float* __restrict__ Out)
{
    extern __shared__ float sm[];
    float* KsBuf = sm;
    float* VsBuf = sm + 2 * KS_TILE;
    float* Pb    = sm + 2 * KS_TILE + 2 * VS_TILE;

    const int tid  = threadIdx.x;
    const int wid  = tid >> 5;          // 0..3
    const int lane = tid & 31;
    const int gi   = lane >> 2;
    const int ti   = lane & 3;
    const int h    = blockIdx.y;
    const int bb   = blockIdx.z;
    const int q0   = blockIdx.x * 128;

    const float* Qbase = Qp + ((size_t)(bb * SEQ + q0)) * EMBED + h * HDIM;
    const float* Kbase = Kp + ((size_t)bb * SEQ) * EMBED + h * HDIM;
    const float* Vbase = Vp + ((size_t)bb * SEQ) * EMBED + h * HDIM;

    // ---- stage Q tile [128 x 64] into Pb ----
    #pragma unroll
    for (int i = 0; i < 16; i++) {
        int f = tid + i * 128;          // 0..2047
        int r = f >> 4, c4 = f & 15;
        cp_async16(&Pb[r * PS_STRIDE + c4 * 4], Qbase + (size_t)r * EMBED + c4 * 4);
    }
    CP_ASYNC_COMMIT();
    CP_ASYNC_WAIT0();
    __syncthreads();

    const float qscale = 0.125f * 1.4426950408889634f;   // 1/sqrt(64)*log2(e)
    float* Pw = Pb + (wid * 32) * PS_STRIDE;             // warp's 32 rows

    uint32_t qf[2][8][4];
    #pragma unroll
    for (int mt = 0; mt < 2; mt++) {
        #pragma unroll
        for (int ks = 0; ks < 8; ks++) {
            int rlo = mt * 16 + gi, rhi = rlo + 8;
            qf[mt][ks][0] = f2tf32(Pw[rlo * PS_STRIDE + ks * 8 + ti] * qscale);
            qf[mt][ks][1] = f2tf32(Pw[rhi * PS_STRIDE + ks * 8 + ti] * qscale);
            qf[mt][ks][2] = f2tf32(Pw[rlo * PS_STRIDE + ks * 8 + ti + 4] * qscale);
            qf[mt][ks][3] = f2tf32(Pw[rhi * PS_STRIDE + ks * 8 + ti + 4] * qscale);
        }
    }
    __syncthreads();   // Pb now free for P round-trips

    float oacc[2][8][4];
    #pragma unroll
    for (int mt = 0; mt < 2; mt++)
        #pragma unroll
        for (int nt = 0; nt < 8; nt++)
            #pragma unroll
            for (int r = 0; r < 4; r++) oacc[mt][nt][r] = 0.0f;
    float mA[2] = {-1e30f, -1e30f}, mB[2] = {-1e30f, -1e30f};
    float lA[2] = {0.0f, 0.0f},     lB[2] = {0.0f, 0.0f};

    auto load_kv = [&](int t, int b) {
        const float* Kt = Kbase + (size_t)(t * 64) * EMBED;
        const float* Vt = Vbase + (size_t)(t * 64) * EMBED;
        float* Kd = KsBuf + b * KS_TILE;
        float* Vd = VsBuf + b * VS_TILE;
        #pragma unroll
        for (int i = 0; i < 8; i++) {
            int f = tid + i * 128;      // 0..1023
            int r = f >> 4, c4 = f & 15;
            cp_async16(&Kd[r * KS_STRIDE + c4 * 4], Kt + (size_t)r * EMBED + c4 * 4);
            cp_async16(&Vd[r * VS_STRIDE + c4 * 4], Vt + (size_t)r * EMBED + c4 * 4);
        }
        CP_ASYNC_COMMIT();
    };

    const int NT = SEQ / 64;
    load_kv(0, 0);
    int buf = 0;

    for (int t = 0; t < NT; t++) {
        if (t + 1 < NT) {
            load_kv(t + 1, buf ^ 1);
            CP_ASYNC_WAIT1();
        } else {
            CP_ASYNC_WAIT0();
        }
        __syncthreads();

        const float* Kd = KsBuf + buf * KS_TILE;
        const float* Vd = VsBuf + buf * VS_TILE;

        // ---- S = Q K^T : K b-frags shared across both m-tiles ----
        float s[2][8][4];
        #pragma unroll
        for (int mt = 0; mt < 2; mt++)
            #pragma unroll
            for (int nt = 0; nt < 8; nt++)
                #pragma unroll
                for (int r = 0; r < 4; r++) s[mt][nt][r] = 0.0f;

        #pragma unroll
        for (int nt = 0; nt < 8; nt++) {
            #pragma unroll
            for (int ks = 0; ks < 8; ks++) {
                uint32_t b0 = __float_as_uint(Kd[(nt * 8 + gi) * KS_STRIDE + ks * 8 + ti]);
                uint32_t b1 = __float_as_uint(Kd[(nt * 8 + gi) * KS_STRIDE + ks * 8 + ti + 4]);
                mma_tf32(s[0][nt][0], s[0][nt][1], s[0][nt][2], s[0][nt][3],
                         qf[0][ks][0], qf[0][ks][1], qf[0][ks][2], qf[0][ks][3], b0, b1);
                mma_tf32(s[1][nt][0], s[1][nt][1], s[1][nt][2], s[1][nt][3],
                         qf[1][ks][0], qf[1][ks][1], qf[1][ks][2], qf[1][ks][3], b0, b1);
            }
        }

        // ---- online softmax per m-tile (rows mt*16+gi and +8) ----
        #pragma unroll
        for (int mt = 0; mt < 2; mt++) {
            float mAt = -1e30f, mBt = -1e30f;
            #pragma unroll
            for (int nt = 0; nt < 8; nt++) {
                mAt = fmaxf(mAt, fmaxf(s[mt][nt][0], s[mt][nt][1]));
                mBt = fmaxf(mBt, fmaxf(s[mt][nt][2], s[mt][nt][3]));
            }
            mAt = fmaxf(mAt, __shfl_xor_sync(0xffffffffu, mAt, 1));
            mAt = fmaxf(mAt, __shfl_xor_sync(0xffffffffu, mAt, 2));
            mBt = fmaxf(mBt, __shfl_xor_sync(0xffffffffu, mBt, 1));
            mBt = fmaxf(mBt, __shfl_xor_sync(0xffffffffu, mBt, 2));

            float mA_new = fmaxf(mA[mt], mAt), mB_new = fmaxf(mB[mt], mBt);
            float cA = ex2(mA[mt] - mA_new), cB = ex2(mB[mt] - mB_new);

            float sA = 0.0f, sB = 0.0f;
            int rlo = mt * 16 + gi, rhi = rlo + 8;
            #pragma unroll
            for (int nt = 0; nt < 8; nt++) {
                float p0 = ex2(s[mt][nt][0] - mA_new);
                float p1 = ex2(s[mt][nt][1] - mA_new);
                float p2 = ex2(s[mt][nt][2] - mB_new);
                float p3 = ex2(s[mt][nt][3] - mB_new);
                sA += p0 + p1; sB += p2 + p3;
                uint2 uA = make_uint2(f2tf32(p0), f2tf32(p1));
                uint2 uB = make_uint2(f2tf32(p2), f2tf32(p3));
                *(uint2*)&Pw[rlo * PS_STRIDE + nt * 8 + 2 * ti] = uA;
                *(uint2*)&Pw[rhi * PS_STRIDE + nt * 8 + 2 * ti] = uB;
            }
            sA += __shfl_xor_sync(0xffffffffu, sA, 1);
            sA += __shfl_xor_sync(0xffffffffu, sA, 2);
            sB += __shfl_xor_sync(0xffffffffu, sB, 1);
            sB += __shfl_xor_sync(0xffffffffu, sB, 2);

            lA[mt] = lA[mt] * cA + sA;
            lB[mt] = lB[mt] * cB + sB;
            mA[mt] = mA_new; mB[mt] = mB_new;

            #pragma unroll
            for (int nt = 0; nt < 8; nt++) {
                oacc[mt][nt][0] *= cA; oacc[mt][nt][1] *= cA;
                oacc[mt][nt][2] *= cB; oacc[mt][nt][3] *= cB;
            }
        }
        __syncwarp();

        // ---- O += P V : V b-frags shared across both m-tiles ----
        #pragma unroll
        for (int ks = 0; ks < 8; ks++) {
            uint32_t bfr[8][2];
            #pragma unroll
            for (int nt = 0; nt < 8; nt++) {
                bfr[nt][0] = __float_as_uint(Vd[(ks * 8 + ti) * VS_STRIDE + nt * 8 + gi]);
                bfr[nt][1] = __float_as_uint(Vd[(ks * 8 + ti + 4) * VS_STRIDE + nt * 8 + gi]);
            }
            #pragma unroll
            for (int mt = 0; mt < 2; mt++) {
                int rlo = mt * 16 + gi, rhi = rlo + 8;
                uint32_t a0 = *(const uint32_t*)&Pw[rlo * PS_STRIDE + ks * 8 + ti];
                uint32_t a1 = *(const uint32_t*)&Pw[rhi * PS_STRIDE + ks * 8 + ti];
                uint32_t a2 = *(const uint32_t*)&Pw[rlo * PS_STRIDE + ks * 8 + ti + 4];
                uint32_t a3 = *(const uint32_t*)&Pw[rhi * PS_STRIDE + ks * 8 + ti + 4];
                #pragma unroll
                for (int nt = 0; nt < 8; nt++)
                    mma_tf32(oacc[mt][nt][0], oacc[mt][nt][1],
                             oacc[mt][nt][2], oacc[mt][nt][3],
                             a0, a1, a2, a3, bfr[nt][0], bfr[nt][1]);
            }
        }
        __syncthreads();
        buf ^= 1;
    }

    // ---- epilogue: normalize + TF32-round (feeds O-projection) ----
    #pragma unroll
    for (int mt = 0; mt < 2; mt++) {
        const float invA = 1.0f / lA[mt], invB = 1.0f / lB[mt];
        const int row0 = q0 + wid * 32 + mt * 16 + gi;
        float* Ob = Out + ((size_t)(bb * SEQ + row0)) * EMBED + h * HDIM;
        #pragma unroll
        for (int nt = 0; nt < 8; nt++) {
            int col = nt * 8 + 2 * ti;
            float2 vA, vB;
            vA.x = __uint_as_float(f2tf32(oacc[mt][nt][0] * invA));
            vA.y = __uint_as_float(f2tf32(oacc[mt][nt][1] * invA));
            vB.x = __uint_as_float(f2tf32(oacc[mt][nt][2] * invB));
            vB.y = __uint_as_float(f2tf32(oacc[mt][nt][3] * invB));
            *(float2*)(Ob + col) = vA;
            *(float2*)(Ob + (size_t)8 * EMBED + col) = vB;
        }
    }
}

// ---------------- launch ----------------------------------------------------
extern "C" void kernel_launch(void* const* d_in, const int* in_sizes, int n_in,
                              void* d_out, int out_size)
{
    const float* q  = (const float*)d_in[0];
    const float* k  = (const float*)d_in[1];
    const float* v  = (const float*)d_in[2];
    const float* Wq = (const float*)d_in[3];
    const float* bq = (const float*)d_in[4];
    const float* Wk = (const float*)d_in[5];
    const float* bk = (const float*)d_in[6];
    const float* Wv = (const float*)d_in[7];
    const float* bv = (const float*)d_in[8];
    const float* Wo = (const float*)d_in[9];
    const float* bo = (const float*)d_in[10];
    float* out = (float*)d_out;

    float *Qp, *Kp, *Vp, *Attn, *qr, *kr, *vr, *Wqr, *Wkr, *Wvr, *Wor;
    cudaGetSymbolAddress((void**)&Qp,   g_Qp);
    cudaGetSymbolAddress((void**)&Kp,   g_Kp);
    cudaGetSymbolAddress((void**)&Vp,   g_Vp);
    cudaGetSymbolAddress((void**)&Attn, g_Attn);
    cudaGetSymbolAddress((void**)&qr,   g_qr);
    cudaGetSymbolAddress((void**)&kr,   g_kr);
    cudaGetSymbolAddress((void**)&vr,   g_vr);
    cudaGetSymbolAddress((void**)&Wqr,  g_Wqr);
    cudaGetSymbolAddress((void**)&Wkr,  g_Wkr);
    cudaGetSymbolAddress((void**)&Wvr,  g_Wvr);
    cudaGetSymbolAddress((void**)&Wor,  g_Wor);

    cudaFuncSetAttribute(attn_mma_kernel,
                         cudaFuncAttributeMaxDynamicSharedMemorySize,
                         ATTN_SMEM_BYTES);

    // pre-round inputs and weights to TF32 (RNA)
    const int BIG4 = MROWS * EMBED / 4;
    const int W4   = EMBED * EMBED / 4;
    round_tf32_vec<<<BIG4 / 256, 256>>>((const float4*)q,  (float4*)qr,  BIG4);
    round_tf32_vec<<<BIG4 / 256, 256>>>((const float4*)k,  (float4*)kr,  BIG4);
    round_tf32_vec<<<BIG4 / 256, 256>>>((const float4*)v,  (float4*)vr,  BIG4);
    round_tf32_vec<<<W4 / 256,  256>>>((const float4*)Wq, (float4*)Wqr, W4);
    round_tf32_vec<<<W4 / 256,  256>>>((const float4*)Wk, (float4*)Wkr, W4);
    round_tf32_vec<<<W4 / 256,  256>>>((const float4*)Wv, (float4*)Wvr, W4);
    round_tf32_vec<<<W4 / 256,  256>>>((const float4*)Wo, (float4*)Wor, W4);

    dim3 gemm_grid(EMBED / GBN, MROWS / GBM);   // (8, 32)
    gemm_tf32_bias<true><<<gemm_grid, 128>>>(qr, Wqr, bq, Qp, MROWS, EMBED, EMBED);
    gemm_tf32_bias<true><<<gemm_grid, 128>>>(kr, Wkr, bk, Kp, MROWS, EMBED, EMBED);
    gemm_tf32_bias<true><<<gemm_grid, 128>>>(vr, Wvr, bv, Vp, MROWS, EMBED, EMBED);

    dim3 attn_grid(SEQ / 128, HEADS, BATCH);    // (16, 16, 2)
    attn_mma_kernel<<<attn_grid, 128, ATTN_SMEM_BYTES>>>(Qp, Kp, Vp, Attn);

    gemm_tf32_bias<false><<<gemm_grid, 128>>>(Attn, Wor, bo, out, MROWS, EMBED, EMBED);
}

// round 7
// speedup vs baseline: 4.7347x; 1.0387x over previous
#include <cuda_runtime.h>
#include <cuda_bf16.h>
#include <math.h>
#include <stdint.h>

// Problem constants
#define BATCH 2
#define SEQ   2048
#define EMBED 1024
#define HEADS 16
#define HDIM  64
#define MROWS (BATCH * SEQ)   // 4096

// ---------------- scratch (device globals; no runtime allocation) ----------
__device__ float g_Qp[MROWS * EMBED];
__device__ float g_Kp[MROWS * EMBED];
__device__ float g_Vp[MROWS * EMBED];
__device__ float g_Attn[MROWS * EMBED];
__device__ float g_qr[MROWS * EMBED];
__device__ float g_kr[MROWS * EMBED];
__device__ float g_vr[MROWS * EMBED];
// TF32-rounded AND transposed weights: Wt[n*K + k] = round(W[k*N + n])
__device__ float g_Wqt[EMBED * EMBED];
__device__ float g_Wkt[EMBED * EMBED];
__device__ float g_Wvt[EMBED * EMBED];
__device__ float g_Wot[EMBED * EMBED];

// ---------------- helpers ---------------------------------------------------
__device__ __forceinline__ uint32_t f2tf32(float x) {
    uint32_t r;
    asm("cvt.rna.tf32.f32 %0, %1;" : "=r"(r) : "f"(x));
    return r;
}

__device__ __forceinline__ float ex2(float x) {
    float r;
    asm("ex2.approx.f32 %0, %1;" : "=f"(r) : "f"(x));
    return r;
}

__device__ __forceinline__ void cp_async16(void* smem_ptr, const void* gmem_ptr) {
    uint32_t s = (uint32_t)__cvta_generic_to_shared(smem_ptr);
    asm volatile("cp.async.cg.shared.global [%0], [%1], 16;\n" :: "r"(s), "l"(gmem_ptr));
}
#define CP_ASYNC_COMMIT() asm volatile("cp.async.commit_group;\n" ::: "memory")
#define CP_ASYNC_WAIT0()  asm volatile("cp.async.wait_group 0;\n" ::: "memory")
#define CP_ASYNC_WAIT1()  asm volatile("cp.async.wait_group 1;\n" ::: "memory")

__device__ __forceinline__ void mma_tf32(float& d0, float& d1, float& d2, float& d3,
                                         uint32_t a0, uint32_t a1, uint32_t a2, uint32_t a3,
                                         uint32_t b0, uint32_t b1) {
    asm volatile(
        "mma.sync.aligned.m16n8k8.row.col.f32.tf32.tf32.f32 "
        "{%0,%1,%2,%3}, {%4,%5,%6,%7}, {%8,%9}, {%0,%1,%2,%3};\n"
        : "+f"(d0), "+f"(d1), "+f"(d2), "+f"(d3)
        : "r"(a0), "r"(a1), "r"(a2), "r"(a3), "r"(b0), "r"(b1));
}

// ldmatrix x4: lane l supplies the address of row (l&7) of matrix (l>>3).
// For 32-bit (tf32) data: one 8x8 b16 matrix == one 8x4 b32 tile; output
// reg r_mi of lane l == element (row l>>2, col l&3) of matrix mi.
__device__ __forceinline__ void ldsm_x4(uint32_t& r0, uint32_t& r1,
                                        uint32_t& r2, uint32_t& r3, uint32_t addr) {
    asm volatile("ldmatrix.sync.aligned.m8n8.x4.shared.b16 {%0,%1,%2,%3}, [%4];"
                 : "=r"(r0), "=r"(r1), "=r"(r2), "=r"(r3) : "r"(addr));
}

// ---------------- pre-passes -------------------------------------------------
// One launch rounds q, k, v (selected by blockIdx.y).
__global__ __launch_bounds__(256)
void round_inputs(const float4* __restrict__ q, const float4* __restrict__ k,
                  const float4* __restrict__ v,
                  float4* __restrict__ qo, float4* __restrict__ ko,
                  float4* __restrict__ vo, int n4)
{
    const float4* in  = (blockIdx.y == 0) ? q  : (blockIdx.y == 1) ? k  : v;
    float4*       out = (blockIdx.y == 0) ? qo : (blockIdx.y == 1) ? ko : vo;
    int i = blockIdx.x * blockDim.x + threadIdx.x;
    if (i < n4) {
        float4 t = in[i];
        t.x = __uint_as_float(f2tf32(t.x));
        t.y = __uint_as_float(f2tf32(t.y));
        t.z = __uint_as_float(f2tf32(t.z));
        t.w = __uint_as_float(f2tf32(t.w));
        out[i] = t;
    }
}

// One launch transposes+rounds all 4 weights (selected by blockIdx.z).
// Wt[n][k] = round_tf32(W[k][n])
__global__ __launch_bounds__(256)
void transpose_round4(const float* __restrict__ W0, const float* __restrict__ W1,
                      const float* __restrict__ W2, const float* __restrict__ W3,
                      float* __restrict__ T0, float* __restrict__ T1,
                      float* __restrict__ T2, float* __restrict__ T3)
{
    __shared__ float tile[32][33];
    const float* W = (blockIdx.z == 0) ? W0 : (blockIdx.z == 1) ? W1
                   : (blockIdx.z == 2) ? W2 : W3;
    float* T = (blockIdx.z == 0) ? T0 : (blockIdx.z == 1) ? T1
             : (blockIdx.z == 2) ? T2 : T3;
    const int tx = threadIdx.x;   // 0..31
    const int ty = threadIdx.y;   // 0..7
    const int k0 = blockIdx.x * 32;
    const int n0 = blockIdx.y * 32;
    #pragma unroll
    for (int j = 0; j < 32; j += 8)
        tile[ty + j][tx] = W[(size_t)(k0 + ty + j) * EMBED + n0 + tx];
    __syncthreads();
    #pragma unroll
    for (int j = 0; j < 32; j += 8)
        T[(size_t)(n0 + ty + j) * EMBED + k0 + tx] =
            __uint_as_float(f2tf32(tile[tx][ty + j]));
}

// ---------------- TF32 tensor-core GEMM: C = A[M,K] @ Bt[N,K]^T + bias -----
// Block tile 128x128, 4 warps, warp tile 64x64, ldmatrix fragment loads.
// Both A and Bt tiles are [row][16 k] padded to stride 20 floats (80B):
// LDSM chunk index 5r+c mod 8 distinct -> conflict-free.
#define GBM 128
#define GBN 128
#define GBK 16
#define T_STRIDE 20            // floats
#define T_ROWB   80            // bytes per row
#define TILE_W   (128 * T_STRIDE)

template<bool ROUND_C>
__global__ __launch_bounds__(128, 2)
void gemm_tf32_bias(const float* __restrict__ A,
                    const float* __restrict__ Bt,
                    const float* __restrict__ bias,
                    float* __restrict__ C,
                    int M, int N, int K)
{
    __shared__ float As[2][TILE_W];
    __shared__ float Bs[2][TILE_W];

    const int tid  = threadIdx.x;
    const int wid  = tid >> 5;
    const int lane = tid & 31;
    const int gi   = lane >> 2;
    const int ti   = lane & 3;
    const int mi   = lane >> 3;   // ldmatrix matrix index 0..3
    const int lr   = lane & 7;    // ldmatrix row within matrix

    const int brow = blockIdx.y;
    const int bcol = blockIdx.x;
    const int warp_m = (wid & 1) * 64;
    const int warp_n = (wid >> 1) * 64;

    const float* Ablk = A  + (size_t)(brow * GBM) * K;
    const float* Bblk = Bt + (size_t)(bcol * GBN) * K;

    const uint32_t AsU = (uint32_t)__cvta_generic_to_shared(&As[0][0]);
    const uint32_t BsU = (uint32_t)__cvta_generic_to_shared(&Bs[0][0]);
    // a-frag ldmatrix lane offset: rowoff=(mi&1)*8, chunkoff=mi>>1
    const uint32_t laneA = (uint32_t)(((mi & 1) * 8 + lr) * T_ROWB + (mi >> 1) * 16);
    // b-frag ldmatrix lane offset: ntoff=(mi>>1)*8, chunkoff=mi&1
    const uint32_t laneB = (uint32_t)(((mi >> 1) * 8 + lr) * T_ROWB + (mi & 1) * 16);

    float acc[4][8][4];
    #pragma unroll
    for (int i = 0; i < 4; i++)
        #pragma unroll
        for (int j = 0; j < 8; j++)
            #pragma unroll
            for (int r = 0; r < 4; r++) acc[i][j][r] = 0.0f;

    const int NIT = K / GBK;

    auto load_tile = [&](int buf, int k0) {
        #pragma unroll
        for (int i = 0; i < 4; i++) {
            int f  = tid + i * 128;       // 0..511
            int r  = f >> 2;              // 0..127
            int c4 = f & 3;
            cp_async16(&As[buf][r * T_STRIDE + c4 * 4],
                       Ablk + (size_t)r * K + k0 + c4 * 4);
            cp_async16(&Bs[buf][r * T_STRIDE + c4 * 4],
                       Bblk + (size_t)r * K + k0 + c4 * 4);
        }
        CP_ASYNC_COMMIT();
    };

    load_tile(0, 0);

    int buf = 0;
    for (int it = 0; it < NIT; it++) {
        CP_ASYNC_WAIT0();
        __syncthreads();
        if (it + 1 < NIT) load_tile(buf ^ 1, (it + 1) * GBK);

        const uint32_t Au = AsU + (uint32_t)buf * (TILE_W * 4);
        const uint32_t Bu = BsU + (uint32_t)buf * (TILE_W * 4);
        #pragma unroll
        for (int ks = 0; ks < GBK; ks += 8) {
            uint32_t afr[4][4];
            #pragma unroll
            for (int mt = 0; mt < 4; mt++)
                ldsm_x4(afr[mt][0], afr[mt][1], afr[mt][2], afr[mt][3],
                        Au + (uint32_t)((warp_m + mt * 16) * T_ROWB + ks * 4) + laneA);
            uint32_t bfr[8][2];
            #pragma unroll
            for (int p = 0; p < 4; p++)
                ldsm_x4(bfr[2 * p][0], bfr[2 * p][1], bfr[2 * p + 1][0], bfr[2 * p + 1][1],
                        Bu + (uint32_t)((warp_n + p * 16) * T_ROWB + ks * 4) + laneB);
            #pragma unroll
            for (int mt = 0; mt < 4; mt++)
                #pragma unroll
                for (int nt = 0; nt < 8; nt++)
                    mma_tf32(acc[mt][nt][0], acc[mt][nt][1],
                             acc[mt][nt][2], acc[mt][nt][3],
                             afr[mt][0], afr[mt][1], afr[mt][2], afr[mt][3],
                             bfr[nt][0], bfr[nt][1]);
        }
        buf ^= 1;
        __syncthreads();
    }

    #pragma unroll
    for (int mt = 0; mt < 4; mt++) {
        int row0 = brow * GBM + warp_m + mt * 16 + gi;
        #pragma unroll
        for (int nt = 0; nt < 8; nt++) {
            int col0 = bcol * GBN + warp_n + nt * 8 + 2 * ti;
            float b0 = bias[col0], b1 = bias[col0 + 1];
            float c00 = acc[mt][nt][0] + b0, c01 = acc[mt][nt][1] + b1;
            float c10 = acc[mt][nt][2] + b0, c11 = acc[mt][nt][3] + b1;
            if (ROUND_C) {
                c00 = __uint_as_float(f2tf32(c00));
                c01 = __uint_as_float(f2tf32(c01));
                c10 = __uint_as_float(f2tf32(c10));
                c11 = __uint_as_float(f2tf32(c11));
            }
            *(float2*)(C + (size_t)row0 * N + col0)       = make_float2(c00, c01);
            *(float2*)(C + (size_t)(row0 + 8) * N + col0) = make_float2(c10, c11);
        }
    }
}

// ---------------- TF32 mma.sync flash attention -----------------------------
// 4 warps, 32 Q rows/warp. K b-frags and P a-frags via ldmatrix.
#define KS_STRIDE 68
#define VS_STRIDE 72
#define PS_STRIDE 68
#define KS_TILE (64 * KS_STRIDE)
#define VS_TILE (64 * VS_STRIDE)
#define ATTN_SMEM_WORDS (2 * KS_TILE + 2 * VS_TILE + 128 * PS_STRIDE)
#define ATTN_SMEM_BYTES (ATTN_SMEM_WORDS * 4)

__global__ __launch_bounds__(128, 2)
void attn_mma_kernel(const float* __restrict__ Qp,
                     const float* __restrict__ Kp,
                     const float* __restrict__ Vp,
                     float* __restrict__ Out)
{
    extern __shared__ float sm[];
    float* KsBuf = sm;
    float* VsBuf = sm + 2 * KS_TILE;
    float* Pb    = sm + 2 * KS_TILE + 2 * VS_TILE;

    const int tid  = threadIdx.x;
    const int wid  = tid >> 5;
    const int lane = tid & 31;
    const int gi   = lane >> 2;
    const int ti   = lane & 3;
    const int mi   = lane >> 3;
    const int lr   = lane & 7;
    const int h    = blockIdx.y;
    const int bb   = blockIdx.z;
    const int q0   = blockIdx.x * 128;

    const float* Qbase = Qp + ((size_t)(bb * SEQ + q0)) * EMBED + h * HDIM;
    const float* Kbase = Kp + ((size_t)bb * SEQ) * EMBED + h * HDIM;
    const float* Vbase = Vp + ((size_t)bb * SEQ) * EMBED + h * HDIM;

    const uint32_t KsU = (uint32_t)__cvta_generic_to_shared(KsBuf);
    const uint32_t PbU = (uint32_t)__cvta_generic_to_shared(Pb);
    const uint32_t PwU = PbU + (uint32_t)((wid * 32) * PS_STRIDE * 4);
    // QK b-frag lane offset: row = nt*8 + lr (key), chunk = 4q + mi (dim/4)
    const uint32_t laneKB = (uint32_t)(lr * (KS_STRIDE * 4) + mi * 16);
    // PV a-frag lane offset: rowoff = (mi&1)*8 + lr, chunkoff = mi>>1
    const uint32_t lanePA = (uint32_t)(((mi & 1) * 8 + lr) * (PS_STRIDE * 4) + (mi >> 1) * 16);

    // ---- stage Q tile [128 x 64] into Pb ----
    #pragma unroll
    for (int i = 0; i < 16; i++) {
        int f = tid + i * 128;
        int r = f >> 4, c4 = f & 15;
        cp_async16(&Pb[r * PS_STRIDE + c4 * 4], Qbase + (size_t)r * EMBED + c4 * 4);
    }
    CP_ASYNC_COMMIT();
    CP_ASYNC_WAIT0();
    __syncthreads();

    const float qscale = 0.125f * 1.4426950408889634f;   // 1/sqrt(64)*log2(e)
    float* Pw = Pb + (wid * 32) * PS_STRIDE;

    uint32_t qf[2][8][4];
    #pragma unroll
    for (int mt = 0; mt < 2; mt++) {
        #pragma unroll
        for (int ks = 0; ks < 8; ks++) {
            int rlo = mt * 16 + gi, rhi = rlo + 8;
            qf[mt][ks][0] = f2tf32(Pw[rlo * PS_STRIDE + ks * 8 + ti] * qscale);
            qf[mt][ks][1] = f2tf32(Pw[rhi * PS_STRIDE + ks * 8 + ti] * qscale);
            qf[mt][ks][2] = f2tf32(Pw[rlo * PS_STRIDE + ks * 8 + ti + 4] * qscale);
            qf[mt][ks][3] = f2tf32(Pw[rhi * PS_STRIDE + ks * 8 + ti + 4] * qscale);
        }
    }
    __syncthreads();

    float oacc[2][8][4];
    #pragma unroll
    for (int mt = 0; mt < 2; mt++)
        #pragma unroll
        for (int nt = 0; nt < 8; nt++)
            #pragma unroll
            for (int r = 0; r < 4; r++) oacc[mt][nt][r] = 0.0f;
    float mA[2] = {-1e30f, -1e30f}, mB[2] = {-1e30f, -1e30f};
    float lA[2] = {0.0f, 0.0f},     lB[2] = {0.0f, 0.0f};

    auto load_kv = [&](int t, int b) {
        const float* Kt = Kbase + (size_t)(t * 64) * EMBED;
        const float* Vt = Vbase + (size_t)(t * 64) * EMBED;
        float* Kd = KsBuf + b * KS_TILE;
        float* Vd = VsBuf + b * VS_TILE;
        #pragma unroll
        for (int i = 0; i < 8; i++) {
            int f = tid + i * 128;
            int r = f >> 4, c4 = f & 15;
            cp_async16(&Kd[r * KS_STRIDE + c4 * 4], Kt + (size_t)r * EMBED + c4 * 4);
            cp_async16(&Vd[r * VS_STRIDE + c4 * 4], Vt + (size_t)r * EMBED + c4 * 4);
        }
        CP_ASYNC_COMMIT();
    };

    const int NT = SEQ / 64;
    load_kv(0, 0);
    int buf = 0;

    for (int t = 0; t < NT; t++) {
        if (t + 1 < NT) {
            load_kv(t + 1, buf ^ 1);
            CP_ASYNC_WAIT1();
        } else {
            CP_ASYNC_WAIT0();
        }
        __syncthreads();

        const uint32_t KdU = KsU + (uint32_t)(buf * KS_TILE * 4);
        const float* Vd = VsBuf + buf * VS_TILE;

        // ---- S = Q K^T : K b-frags via ldmatrix (4 x4 per nt = 16 regs) ----
        float s[2][8][4];
        #pragma unroll
        for (int nt = 0; nt < 8; nt++) {
            uint32_t kb[16];   // kb[c] = 16B chunk c of this nt's key rows: ks=c>>1, half=c&1
            uint32_t base = KdU + (uint32_t)(nt * 8 * KS_STRIDE * 4) + laneKB;
            #pragma unroll
            for (int q = 0; q < 4; q++)
                ldsm_x4(kb[4 * q], kb[4 * q + 1], kb[4 * q + 2], kb[4 * q + 3],
                        base + (uint32_t)(q * 64));
            #pragma unroll
            for (int r = 0; r < 4; r++) { s[0][nt][r] = 0.0f; s[1][nt][r] = 0.0f; }
            #pragma unroll
            for (int ks = 0; ks < 8; ks++) {
                mma_tf32(s[0][nt][0], s[0][nt][1], s[0][nt][2], s[0][nt][3],
                         qf[0][ks][0], qf[0][ks][1], qf[0][ks][2], qf[0][ks][3],
                         kb[2 * ks], kb[2 * ks + 1]);
                mma_tf32(s[1][nt][0], s[1][nt][1], s[1][nt][2], s[1][nt][3],
                         qf[1][ks][0], qf[1][ks][1], qf[1][ks][2], qf[1][ks][3],
                         kb[2 * ks], kb[2 * ks + 1]);
            }
        }

        // ---- online softmax per m-tile ----
        #pragma unroll
        for (int mt = 0; mt < 2; mt++) {
            float mAt = -1e30f, mBt = -1e30f;
            #pragma unroll
            for (int nt = 0; nt < 8; nt++) {
                mAt = fmaxf(mAt, fmaxf(s[mt][nt][0], s[mt][nt][1]));
                mBt = fmaxf(mBt, fmaxf(s[mt][nt][2], s[mt][nt][3]));
            }
            mAt = fmaxf(mAt, __shfl_xor_sync(0xffffffffu, mAt, 1));
            mAt = fmaxf(mAt, __shfl_xor_sync(0xffffffffu, mAt, 2));
            mBt = fmaxf(mBt, __shfl_xor_sync(0xffffffffu, mBt, 1));
            mBt = fmaxf(mBt, __shfl_xor_sync(0xffffffffu, mBt, 2));

            float mA_new = fmaxf(mA[mt], mAt), mB_new = fmaxf(mB[mt], mBt);
            float cA = ex2(mA[mt] - mA_new), cB = ex2(mB[mt] - mB_new);

            float sA = 0.0f, sB = 0.0f;
            int rlo = mt * 16 + gi, rhi = rlo + 8;
            #pragma unroll
            for (int nt = 0; nt < 8; nt++) {
                float p0 = ex2(s[mt][nt][0] - mA_new);
                float p1 = ex2(s[mt][nt][1] - mA_new);
                float p2 = ex2(s[mt][nt][2] - mB_new);
                float p3 = ex2(s[mt][nt][3] - mB_new);
                sA += p0 + p1; sB += p2 + p3;
                uint2 uA = make_uint2(f2tf32(p0), f2tf32(p1));
                uint2 uB = make_uint2(f2tf32(p2), f2tf32(p3));
                *(uint2*)&Pw[rlo * PS_STRIDE + nt * 8 + 2 * ti] = uA;
                *(uint2*)&Pw[rhi * PS_STRIDE + nt * 8 + 2 * ti] = uB;
            }
            sA += __shfl_xor_sync(0xffffffffu, sA, 1);
            sA += __shfl_xor_sync(0xffffffffu, sA, 2);
            sB += __shfl_xor_sync(0xffffffffu, sB, 1);
            sB += __shfl_xor_sync(0xffffffffu, sB, 2);

            lA[mt] = lA[mt] * cA + sA;
            lB[mt] = lB[mt] * cB + sB;
            mA[mt] = mA_new; mB[mt] = mB_new;

            #pragma unroll
            for (int nt = 0; nt < 8; nt++) {
                oacc[mt][nt][0] *= cA; oacc[mt][nt][1] *= cA;
                oacc[mt][nt][2] *= cB; oacc[mt][nt][3] *= cB;
            }
        }
        __syncwarp();

        // ---- O += P V : P a-frags via ldmatrix, V b-frags scalar ----
        #pragma unroll
        for (int ks = 0; ks < 8; ks++) {
            uint32_t bfr[8][2];
            #pragma unroll
            for (int nt = 0; nt < 8; nt++) {
                bfr[nt][0] = __float_as_uint(Vd[(ks * 8 + ti) * VS_STRIDE + nt * 8 + gi]);
                bfr[nt][1] = __float_as_uint(Vd[(ks * 8 + ti + 4) * VS_STRIDE + nt * 8 + gi]);
            }
            #pragma unroll
            for (int mt = 0; mt < 2; mt++) {
                uint32_t a[4];
                ldsm_x4(a[0], a[1], a[2], a[3],
                        PwU + (uint32_t)(mt * 16 * PS_STRIDE * 4 + ks * 32) + lanePA);
                #pragma unroll
                for (int nt = 0; nt < 8; nt++)
                    mma_tf32(oacc[mt][nt][0], oacc[mt][nt][1],
                             oacc[mt][nt][2], oacc[mt][nt][3],
                             a[0], a[1], a[2], a[3], bfr[nt][0], bfr[nt][1]);
            }
        }
        __syncthreads();
        buf ^= 1;
    }

    // ---- epilogue: normalize + TF32-round (feeds O-projection) ----
    #pragma unroll
    for (int mt = 0; mt < 2; mt++) {
        const float invA = 1.0f / lA[mt], invB = 1.0f / lB[mt];
        const int row0 = q0 + wid * 32 + mt * 16 + gi;
        float* Ob = Out + ((size_t)(bb * SEQ + row0)) * EMBED + h * HDIM;
        #pragma unroll
        for (int nt = 0; nt < 8; nt++) {
            int col = nt * 8 + 2 * ti;
            float2 vA, vB;
            vA.x = __uint_as_float(f2tf32(oacc[mt][nt][0] * invA));
            vA.y = __uint_as_float(f2tf32(oacc[mt][nt][1] * invA));
            vB.x = __uint_as_float(f2tf32(oacc[mt][nt][2] * invB));
            vB.y = __uint_as_float(f2tf32(oacc[mt][nt][3] * invB));
            *(float2*)(Ob + col) = vA;
            *(float2*)(Ob + (size_t)8 * EMBED + col) = vB;
        }
    }
}

// ---------------- launch ----------------------------------------------------
extern "C" void kernel_launch(void* const* d_in, const int* in_sizes, int n_in,
                              void* d_out, int out_size)
{
    const float* q  = (const float*)d_in[0];
    const float* k  = (const float*)d_in[1];
    const float* v  = (const float*)d_in[2];
    const float* Wq = (const float*)d_in[3];
    const float* bq = (const float*)d_in[4];
    const float* Wk = (const float*)d_in[5];
    const float* bk = (const float*)d_in[6];
    const float* Wv = (const float*)d_in[7];
    const float* bv = (const float*)d_in[8];
    const float* Wo = (const float*)d_in[9];
    const float* bo = (const float*)d_in[10];
    float* out = (float*)d_out;

    float *Qp, *Kp, *Vp, *Attn, *qr, *kr, *vr, *Wqt, *Wkt, *Wvt, *Wot;
    cudaGetSymbolAddress((void**)&Qp,   g_Qp);
    cudaGetSymbolAddress((void**)&Kp,   g_Kp);
    cudaGetSymbolAddress((void**)&Vp,   g_Vp);
    cudaGetSymbolAddress((void**)&Attn, g_Attn);
    cudaGetSymbolAddress((void**)&qr,   g_qr);
    cudaGetSymbolAddress((void**)&kr,   g_kr);
    cudaGetSymbolAddress((void**)&vr,   g_vr);
    cudaGetSymbolAddress((void**)&Wqt,  g_Wqt);
    cudaGetSymbolAddress((void**)&Wkt,  g_Wkt);
    cudaGetSymbolAddress((void**)&Wvt,  g_Wvt);
    cudaGetSymbolAddress((void**)&Wot,  g_Wot);

    cudaFuncSetAttribute(attn_mma_kernel,
                         cudaFuncAttributeMaxDynamicSharedMemorySize,
                         ATTN_SMEM_BYTES);

    // pre-round inputs (one launch), round+transpose weights (one launch)
    const int BIG4 = MROWS * EMBED / 4;
    dim3 rgrid(BIG4 / 256, 3);
    round_inputs<<<rgrid, 256>>>((const float4*)q, (const float4*)k, (const float4*)v,
                                 (float4*)qr, (float4*)kr, (float4*)vr, BIG4);
    dim3 tgrid(EMBED / 32, EMBED / 32, 4);
    dim3 tblk(32, 8);
    transpose_round4<<<tgrid, tblk>>>(Wq, Wk, Wv, Wo, Wqt, Wkt, Wvt, Wot);

    dim3 gemm_grid(EMBED / GBN, MROWS / GBM);   // (8, 32)
    gemm_tf32_bias<true><<<gemm_grid, 128>>>(qr, Wqt, bq, Qp, MROWS, EMBED, EMBED);
    gemm_tf32_bias<true><<<gemm_grid, 128>>>(kr, Wkt, bk, Kp, MROWS, EMBED, EMBED);
    gemm_tf32_bias<true><<<gemm_grid, 128>>>(vr, Wvt, bv, Vp, MROWS, EMBED, EMBED);

    dim3 attn_grid(SEQ / 128, HEADS, BATCH);    // (16, 16, 2)
    attn_mma_kernel<<<attn_grid, 128, ATTN_SMEM_BYTES>>>(Qp, Kp, Vp, Attn);

    gemm_tf32_bias<false><<<gemm_grid, 128>>>(Attn, Wot, bo, out, MROWS, EMBED, EMBED);
}

// round 8
// speedup vs baseline: 4.7669x; 1.0068x over previous
#include <cuda_runtime.h>
#include <cuda_bf16.h>
#include <math.h>
#include <stdint.h>

// Problem constants
#define BATCH 2
#define SEQ   2048
#define EMBED 1024
#define HEADS 16
#define HDIM  64
#define MROWS (BATCH * SEQ)   // 4096

// ---------------- scratch (device globals; no runtime allocation) ----------
__device__ float g_Qp[MROWS * EMBED];
__device__ float g_Kp[MROWS * EMBED];
__device__ float g_Vt[MROWS * EMBED];   // V projected, stored [bb][h][d][seq]
__device__ float g_Attn[MROWS * EMBED];
__device__ float g_qr[MROWS * EMBED];
__device__ float g_kr[MROWS * EMBED];
__device__ float g_vr[MROWS * EMBED];
// TF32-rounded AND transposed weights: Wt[n*K + k] = round(W[k*N + n])
__device__ float g_Wqt[EMBED * EMBED];
__device__ float g_Wkt[EMBED * EMBED];
__device__ float g_Wvt[EMBED * EMBED];
__device__ float g_Wot[EMBED * EMBED];

// ---------------- helpers ---------------------------------------------------
__device__ __forceinline__ uint32_t f2tf32(float x) {
    uint32_t r;
    asm("cvt.rna.tf32.f32 %0, %1;" : "=r"(r) : "f"(x));
    return r;
}

__device__ __forceinline__ float ex2(float x) {
    float r;
    asm("ex2.approx.f32 %0, %1;" : "=f"(r) : "f"(x));
    return r;
}

__device__ __forceinline__ void cp_async16(void* smem_ptr, const void* gmem_ptr) {
    uint32_t s = (uint32_t)__cvta_generic_to_shared(smem_ptr);
    asm volatile("cp.async.cg.shared.global [%0], [%1], 16;\n" :: "r"(s), "l"(gmem_ptr));
}
#define CP_ASYNC_COMMIT() asm volatile("cp.async.commit_group;\n" ::: "memory")
#define CP_ASYNC_WAIT0()  asm volatile("cp.async.wait_group 0;\n" ::: "memory")
#define CP_ASYNC_WAIT1()  asm volatile("cp.async.wait_group 1;\n" ::: "memory")

__device__ __forceinline__ void mma_tf32(float& d0, float& d1, float& d2, float& d3,
                                         uint32_t a0, uint32_t a1, uint32_t a2, uint32_t a3,
                                         uint32_t b0, uint32_t b1) {
    asm volatile(
        "mma.sync.aligned.m16n8k8.row.col.f32.tf32.tf32.f32 "
        "{%0,%1,%2,%3}, {%4,%5,%6,%7}, {%8,%9}, {%0,%1,%2,%3};\n"
        : "+f"(d0), "+f"(d1), "+f"(d2), "+f"(d3)
        : "r"(a0), "r"(a1), "r"(a2), "r"(a3), "r"(b0), "r"(b1));
}

__device__ __forceinline__ void ldsm_x4(uint32_t& r0, uint32_t& r1,
                                        uint32_t& r2, uint32_t& r3, uint32_t addr) {
    asm volatile("ldmatrix.sync.aligned.m8n8.x4.shared.b16 {%0,%1,%2,%3}, [%4];"
                 : "=r"(r0), "=r"(r1), "=r"(r2), "=r"(r3) : "r"(addr));
}

// ---------------- pre-passes -------------------------------------------------
__global__ __launch_bounds__(256)
void round_inputs(const float4* __restrict__ q, const float4* __restrict__ k,
                  const float4* __restrict__ v,
                  float4* __restrict__ qo, float4* __restrict__ ko,
                  float4* __restrict__ vo, int n4)
{
    const float4* in  = (blockIdx.y == 0) ? q  : (blockIdx.y == 1) ? k  : v;
    float4*       out = (blockIdx.y == 0) ? qo : (blockIdx.y == 1) ? ko : vo;
    int i = blockIdx.x * blockDim.x + threadIdx.x;
    if (i < n4) {
        float4 t = in[i];
        t.x = __uint_as_float(f2tf32(t.x));
        t.y = __uint_as_float(f2tf32(t.y));
        t.z = __uint_as_float(f2tf32(t.z));
        t.w = __uint_as_float(f2tf32(t.w));
        out[i] = t;
    }
}

// Wt[n][k] = round_tf32(W[k][n])
__global__ __launch_bounds__(256)
void transpose_round4(const float* __restrict__ W0, const float* __restrict__ W1,
                      const float* __restrict__ W2, const float* __restrict__ W3,
                      float* __restrict__ T0, float* __restrict__ T1,
                      float* __restrict__ T2, float* __restrict__ T3)
{
    __shared__ float tile[32][33];
    const float* W = (blockIdx.z == 0) ? W0 : (blockIdx.z == 1) ? W1
                   : (blockIdx.z == 2) ? W2 : W3;
    float* T = (blockIdx.z == 0) ? T0 : (blockIdx.z == 1) ? T1
             : (blockIdx.z == 2) ? T2 : T3;
    const int tx = threadIdx.x;
    const int ty = threadIdx.y;
    const int k0 = blockIdx.x * 32;
    const int n0 = blockIdx.y * 32;
    #pragma unroll
    for (int j = 0; j < 32; j += 8)
        tile[ty + j][tx] = W[(size_t)(k0 + ty + j) * EMBED + n0 + tx];
    __syncthreads();
    #pragma unroll
    for (int j = 0; j < 32; j += 8)
        T[(size_t)(n0 + ty + j) * EMBED + k0 + tx] =
            __uint_as_float(f2tf32(tile[tx][ty + j]));
}

// ---------------- TF32 tensor-core GEMM: C = A[M,K] @ Bt[N,K]^T + bias -----
// MODE: 0 = plain store, 1 = round+store, 2 = round+store transposed-per-head
//       (Vt[((bb*16+h)*64+d)*2048 + seq])
#define GBM 128
#define GBN 128
#define GBK 16
#define T_STRIDE 20
#define T_ROWB   80
#define TILE_W   (128 * T_STRIDE)

template<int MODE>
__global__ __launch_bounds__(128, 2)
void gemm_tf32_bias(const float* __restrict__ A,
                    const float* __restrict__ Bt,
                    const float* __restrict__ bias,
                    float* __restrict__ C,
                    int M, int N, int K)
{
    __shared__ float As[2][TILE_W];
    __shared__ float Bs[2][TILE_W];

    const int tid  = threadIdx.x;
    const int wid  = tid >> 5;
    const int lane = tid & 31;
    const int gi   = lane >> 2;
    const int ti   = lane & 3;
    const int mi   = lane >> 3;
    const int lr   = lane & 7;

    const int brow = blockIdx.y;
    const int bcol = blockIdx.x;
    const int warp_m = (wid & 1) * 64;
    const int warp_n = (wid >> 1) * 64;

    const float* Ablk = A  + (size_t)(brow * GBM) * K;
    const float* Bblk = Bt + (size_t)(bcol * GBN) * K;

    const uint32_t AsU = (uint32_t)__cvta_generic_to_shared(&As[0][0]);
    const uint32_t BsU = (uint32_t)__cvta_generic_to_shared(&Bs[0][0]);
    const uint32_t laneA = (uint32_t)(((mi & 1) * 8 + lr) * T_ROWB + (mi >> 1) * 16);
    const uint32_t laneB = (uint32_t)(((mi >> 1) * 8 + lr) * T_ROWB + (mi & 1) * 16);

    float acc[4][8][4];
    #pragma unroll
    for (int i = 0; i < 4; i++)
        #pragma unroll
        for (int j = 0; j < 8; j++)
            #pragma unroll
            for (int r = 0; r < 4; r++) acc[i][j][r] = 0.0f;

    const int NIT = K / GBK;

    auto load_tile = [&](int buf, int k0) {
        #pragma unroll
        for (int i = 0; i < 4; i++) {
            int f  = tid + i * 128;
            int r  = f >> 2;
            int c4 = f & 3;
            cp_async16(&As[buf][r * T_STRIDE + c4 * 4],
                       Ablk + (size_t)r * K + k0 + c4 * 4);
            cp_async16(&Bs[buf][r * T_STRIDE + c4 * 4],
                       Bblk + (size_t)r * K + k0 + c4 * 4);
        }
        CP_ASYNC_COMMIT();
    };

    load_tile(0, 0);

    int buf = 0;
    for (int it = 0; it < NIT; it++) {
        CP_ASYNC_WAIT0();
        __syncthreads();
        if (it + 1 < NIT) load_tile(buf ^ 1, (it + 1) * GBK);

        const uint32_t Au = AsU + (uint32_t)buf * (TILE_W * 4);
        const uint32_t Bu = BsU + (uint32_t)buf * (TILE_W * 4);
        #pragma unroll
        for (int ks = 0; ks < GBK; ks += 8) {
            uint32_t afr[4][4];
            #pragma unroll
            for (int mt = 0; mt < 4; mt++)
                ldsm_x4(afr[mt][0], afr[mt][1], afr[mt][2], afr[mt][3],
                        Au + (uint32_t)((warp_m + mt * 16) * T_ROWB + ks * 4) + laneA);
            uint32_t bfr[8][2];
            #pragma unroll
            for (int p = 0; p < 4; p++)
                ldsm_x4(bfr[2 * p][0], bfr[2 * p][1], bfr[2 * p + 1][0], bfr[2 * p + 1][1],
                        Bu + (uint32_t)((warp_n + p * 16) * T_ROWB + ks * 4) + laneB);
            #pragma unroll
            for (int mt = 0; mt < 4; mt++)
                #pragma unroll
                for (int nt = 0; nt < 8; nt++)
                    mma_tf32(acc[mt][nt][0], acc[mt][nt][1],
                             acc[mt][nt][2], acc[mt][nt][3],
                             afr[mt][0], afr[mt][1], afr[mt][2], afr[mt][3],
                             bfr[nt][0], bfr[nt][1]);
        }
        buf ^= 1;
        __syncthreads();
    }

    #pragma unroll
    for (int mt = 0; mt < 4; mt++) {
        int row0 = brow * GBM + warp_m + mt * 16 + gi;
        #pragma unroll
        for (int nt = 0; nt < 8; nt++) {
            int col0 = bcol * GBN + warp_n + nt * 8 + 2 * ti;
            float b0 = bias[col0], b1 = bias[col0 + 1];
            float c00 = acc[mt][nt][0] + b0, c01 = acc[mt][nt][1] + b1;
            float c10 = acc[mt][nt][2] + b0, c11 = acc[mt][nt][3] + b1;
            if (MODE >= 1) {
                c00 = __uint_as_float(f2tf32(c00));
                c01 = __uint_as_float(f2tf32(c01));
                c10 = __uint_as_float(f2tf32(c10));
                c11 = __uint_as_float(f2tf32(c11));
            }
            if (MODE == 2) {
                // Vt[((bb*16+h)*64+d)*2048 + seq]; h=col>>6, d=col&63,
                // bb=row>>11, seq=row&2047
                int h  = col0 >> 6;
                int d0 = col0 & 63;
                #pragma unroll
                for (int rr = 0; rr < 2; rr++) {
                    int row = row0 + rr * 8;
                    int bb  = row >> 11, seq = row & 2047;
                    size_t base = ((size_t)((bb * HEADS + h) * HDIM)) * SEQ + seq;
                    float v0 = rr ? c10 : c00;
                    float v1 = rr ? c11 : c01;
                    C[base + (size_t)d0 * SEQ]       = v0;
                    C[base + (size_t)(d0 + 1) * SEQ] = v1;
                }
            } else {
                *(float2*)(C + (size_t)row0 * N + col0)       = make_float2(c00, c01);
                *(float2*)(C + (size_t)(row0 + 8) * N + col0) = make_float2(c10, c11);
            }
        }
    }
}

// ---------------- TF32 mma.sync flash attention -----------------------------
// 4 warps, 32 Q rows/warp. K b-frags, P a-frags AND V b-frags via ldmatrix
// (V is pre-transposed per head: Vt[d][seq]).
#define KS_STRIDE 68
#define VT_STRIDE 68
#define PS_STRIDE 68
#define KS_TILE (64 * KS_STRIDE)
#define VT_TILE (64 * VT_STRIDE)
#define ATTN_SMEM_WORDS (2 * KS_TILE + 2 * VT_TILE + 128 * PS_STRIDE)
#define ATTN_SMEM_BYTES (ATTN_SMEM_WORDS * 4)

__global__ __launch_bounds__(128, 2)
void attn_mma_kernel(const float* __restrict__ Qp,
                     const float* __restrict__ Kp,
                     const float* __restrict__ Vt,
                     float* __restrict__ Out)
{
    extern __shared__ float sm[];
    float* KsBuf = sm;
    float* VsBuf = sm + 2 * KS_TILE;
    float* Pb    = sm + 2 * KS_TILE + 2 * VT_TILE;

    const int tid  = threadIdx.x;
    const int wid  = tid >> 5;
    const int lane = tid & 31;
    const int gi   = lane >> 2;
    const int ti   = lane & 3;
    const int mi   = lane >> 3;
    const int lr   = lane & 7;
    const int h    = blockIdx.y;
    const int bb   = blockIdx.z;
    const int q0   = blockIdx.x * 128;

    const float* Qbase  = Qp + ((size_t)(bb * SEQ + q0)) * EMBED + h * HDIM;
    const float* Kbase  = Kp + ((size_t)bb * SEQ) * EMBED + h * HDIM;
    const float* Vtbase = Vt + ((size_t)((bb * HEADS + h) * HDIM)) * SEQ;  // [64][2048]

    const uint32_t KsU = (uint32_t)__cvta_generic_to_shared(KsBuf);
    const uint32_t VsU = (uint32_t)__cvta_generic_to_shared(VsBuf);
    const uint32_t PbU = (uint32_t)__cvta_generic_to_shared(Pb);
    const uint32_t PwU = PbU + (uint32_t)((wid * 32) * PS_STRIDE * 4);
    // K/V b-frag lane offset: matrix rows along tile rows, chunks along cols
    const uint32_t laneKB = (uint32_t)(lr * (KS_STRIDE * 4) + mi * 16);
    const uint32_t laneVB = (uint32_t)(lr * (VT_STRIDE * 4) + mi * 16);
    // P a-frag lane offset
    const uint32_t lanePA = (uint32_t)(((mi & 1) * 8 + lr) * (PS_STRIDE * 4) + (mi >> 1) * 16);

    // ---- stage Q tile [128 x 64] into Pb ----
    #pragma unroll
    for (int i = 0; i < 16; i++) {
        int f = tid + i * 128;
        int r = f >> 4, c4 = f & 15;
        cp_async16(&Pb[r * PS_STRIDE + c4 * 4], Qbase + (size_t)r * EMBED + c4 * 4);
    }
    CP_ASYNC_COMMIT();
    CP_ASYNC_WAIT0();
    __syncthreads();

    const float qscale = 0.125f * 1.4426950408889634f;
    float* Pw = Pb + (wid * 32) * PS_STRIDE;

    uint32_t qf[2][8][4];
    #pragma unroll
    for (int mt = 0; mt < 2; mt++) {
        #pragma unroll
        for (int ks = 0; ks < 8; ks++) {
            int rlo = mt * 16 + gi, rhi = rlo + 8;
            qf[mt][ks][0] = f2tf32(Pw[rlo * PS_STRIDE + ks * 8 + ti] * qscale);
            qf[mt][ks][1] = f2tf32(Pw[rhi * PS_STRIDE + ks * 8 + ti] * qscale);
            qf[mt][ks][2] = f2tf32(Pw[rlo * PS_STRIDE + ks * 8 + ti + 4] * qscale);
            qf[mt][ks][3] = f2tf32(Pw[rhi * PS_STRIDE + ks * 8 + ti + 4] * qscale);
        }
    }
    __syncthreads();

    float oacc[2][8][4];
    #pragma unroll
    for (int mt = 0; mt < 2; mt++)
        #pragma unroll
        for (int nt = 0; nt < 8; nt++)
            #pragma unroll
            for (int r = 0; r < 4; r++) oacc[mt][nt][r] = 0.0f;
    float mA[2] = {-1e30f, -1e30f}, mB[2] = {-1e30f, -1e30f};
    float lA[2] = {0.0f, 0.0f},     lB[2] = {0.0f, 0.0f};

    auto load_kv = [&](int t, int b) {
        const float* Kt = Kbase + (size_t)(t * 64) * EMBED;
        const float* Vg = Vtbase + t * 64;      // keys t*64.. along the seq axis
        float* Kd = KsBuf + b * KS_TILE;
        float* Vd = VsBuf + b * VT_TILE;
        #pragma unroll
        for (int i = 0; i < 8; i++) {
            int f = tid + i * 128;
            int r = f >> 4, c4 = f & 15;
            cp_async16(&Kd[r * KS_STRIDE + c4 * 4], Kt + (size_t)r * EMBED + c4 * 4);
            cp_async16(&Vd[r * VT_STRIDE + c4 * 4], Vg + (size_t)r * SEQ + c4 * 4);
        }
        CP_ASYNC_COMMIT();
    };

    const int NT = SEQ / 64;
    load_kv(0, 0);
    int buf = 0;

    for (int t = 0; t < NT; t++) {
        if (t + 1 < NT) {
            load_kv(t + 1, buf ^ 1);
            CP_ASYNC_WAIT1();
        } else {
            CP_ASYNC_WAIT0();
        }
        __syncthreads();

        const uint32_t KdU = KsU + (uint32_t)(buf * KS_TILE * 4);
        const uint32_t VdU = VsU + (uint32_t)(buf * VT_TILE * 4);

        // ---- S = Q K^T ----
        float s[2][8][4];
        #pragma unroll
        for (int nt = 0; nt < 8; nt++) {
            uint32_t kb[16];
            uint32_t base = KdU + (uint32_t)(nt * 8 * KS_STRIDE * 4) + laneKB;
            #pragma unroll
            for (int q = 0; q < 4; q++)
                ldsm_x4(kb[4 * q], kb[4 * q + 1], kb[4 * q + 2], kb[4 * q + 3],
                        base + (uint32_t)(q * 64));
            #pragma unroll
            for (int r = 0; r < 4; r++) { s[0][nt][r] = 0.0f; s[1][nt][r] = 0.0f; }
            #pragma unroll
            for (int ks = 0; ks < 8; ks++) {
                mma_tf32(s[0][nt][0], s[0][nt][1], s[0][nt][2], s[0][nt][3],
                         qf[0][ks][0], qf[0][ks][1], qf[0][ks][2], qf[0][ks][3],
                         kb[2 * ks], kb[2 * ks + 1]);
                mma_tf32(s[1][nt][0], s[1][nt][1], s[1][nt][2], s[1][nt][3],
                         qf[1][ks][0], qf[1][ks][1], qf[1][ks][2], qf[1][ks][3],
                         kb[2 * ks], kb[2 * ks + 1]);
            }
        }

        // ---- online softmax per m-tile ----
        #pragma unroll
        for (int mt = 0; mt < 2; mt++) {
            float mAt = -1e30f, mBt = -1e30f;
            #pragma unroll
            for (int nt = 0; nt < 8; nt++) {
                mAt = fmaxf(mAt, fmaxf(s[mt][nt][0], s[mt][nt][1]));
                mBt = fmaxf(mBt, fmaxf(s[mt][nt][2], s[mt][nt][3]));
            }
            mAt = fmaxf(mAt, __shfl_xor_sync(0xffffffffu, mAt, 1));
            mAt = fmaxf(mAt, __shfl_xor_sync(0xffffffffu, mAt, 2));
            mBt = fmaxf(mBt, __shfl_xor_sync(0xffffffffu, mBt, 1));
            mBt = fmaxf(mBt, __shfl_xor_sync(0xffffffffu, mBt, 2));

            float mA_new = fmaxf(mA[mt], mAt), mB_new = fmaxf(mB[mt], mBt);
            float cA = ex2(mA[mt] - mA_new), cB = ex2(mB[mt] - mB_new);

            float sA = 0.0f, sB = 0.0f;
            int rlo = mt * 16 + gi, rhi = rlo + 8;
            #pragma unroll
            for (int nt = 0; nt < 8; nt++) {
                float p0 = ex2(s[mt][nt][0] - mA_new);
                float p1 = ex2(s[mt][nt][1] - mA_new);
                float p2 = ex2(s[mt][nt][2] - mB_new);
                float p3 = ex2(s[mt][nt][3] - mB_new);
                sA += p0 + p1; sB += p2 + p3;
                uint2 uA = make_uint2(f2tf32(p0), f2tf32(p1));
                uint2 uB = make_uint2(f2tf32(p2), f2tf32(p3));
                *(uint2*)&Pw[rlo * PS_STRIDE + nt * 8 + 2 * ti] = uA;
                *(uint2*)&Pw[rhi * PS_STRIDE + nt * 8 + 2 * ti] = uB;
            }
            sA += __shfl_xor_sync(0xffffffffu, sA, 1);
            sA += __shfl_xor_sync(0xffffffffu, sA, 2);
            sB += __shfl_xor_sync(0xffffffffu, sB, 1);
            sB += __shfl_xor_sync(0xffffffffu, sB, 2);

            lA[mt] = lA[mt] * cA + sA;
            lB[mt] = lB[mt] * cB + sB;
            mA[mt] = mA_new; mB[mt] = mB_new;

            #pragma unroll
            for (int nt = 0; nt < 8; nt++) {
                oacc[mt][nt][0] *= cA; oacc[mt][nt][1] *= cA;
                oacc[mt][nt][2] *= cB; oacc[mt][nt][3] *= cB;
            }
        }
        __syncwarp();

        // ---- O += P V : P a-frags hoisted (16 LDSM), V b-frags via ldmatrix ----
        uint32_t pa[2][8][4];
        #pragma unroll
        for (int mt = 0; mt < 2; mt++)
            #pragma unroll
            for (int ks = 0; ks < 8; ks++)
                ldsm_x4(pa[mt][ks][0], pa[mt][ks][1], pa[mt][ks][2], pa[mt][ks][3],
                        PwU + (uint32_t)(mt * 16 * PS_STRIDE * 4 + ks * 32) + lanePA);

        #pragma unroll
        for (int nt = 0; nt < 8; nt++) {      // nt = output-dim group (rows of Vt)
            uint32_t vb[16];
            uint32_t base = VdU + (uint32_t)(nt * 8 * VT_STRIDE * 4) + laneVB;
            #pragma unroll
            for (int q = 0; q < 4; q++)
                ldsm_x4(vb[4 * q], vb[4 * q + 1], vb[4 * q + 2], vb[4 * q + 3],
                        base + (uint32_t)(q * 64));
            #pragma unroll
            for (int ks = 0; ks < 8; ks++) {
                mma_tf32(oacc[0][nt][0], oacc[0][nt][1], oacc[0][nt][2], oacc[0][nt][3],
                         pa[0][ks][0], pa[0][ks][1], pa[0][ks][2], pa[0][ks][3],
                         vb[2 * ks], vb[2 * ks + 1]);
                mma_tf32(oacc[1][nt][0], oacc[1][nt][1], oacc[1][nt][2], oacc[1][nt][3],
                         pa[1][ks][0], pa[1][ks][1], pa[1][ks][2], pa[1][ks][3],
                         vb[2 * ks], vb[2 * ks + 1]);
            }
        }
        __syncthreads();
        buf ^= 1;
    }

    // ---- epilogue: normalize + TF32-round (feeds O-projection) ----
    #pragma unroll
    for (int mt = 0; mt < 2; mt++) {
        const float invA = 1.0f / lA[mt], invB = 1.0f / lB[mt];
        const int row0 = q0 + wid * 32 + mt * 16 + gi;
        float* Ob = Out + ((size_t)(bb * SEQ + row0)) * EMBED + h * HDIM;
        #pragma unroll
        for (int nt = 0; nt < 8; nt++) {
            int col = nt * 8 + 2 * ti;
            float2 vA, vB;
            vA.x = __uint_as_float(f2tf32(oacc[mt][nt][0] * invA));
            vA.y = __uint_as_float(f2tf32(oacc[mt][nt][1] * invA));
            vB.x = __uint_as_float(f2tf32(oacc[mt][nt][2] * invB));
            vB.y = __uint_as_float(f2tf32(oacc[mt][nt][3] * invB));
            *(float2*)(Ob + col) = vA;
            *(float2*)(Ob + (size_t)8 * EMBED + col) = vB;
        }
    }
}

// ---------------- launch ----------------------------------------------------
extern "C" void kernel_launch(void* const* d_in, const int* in_sizes, int n_in,
                              void* d_out, int out_size)
{
    const float* q  = (const float*)d_in[0];
    const float* k  = (const float*)d_in[1];
    const float* v  = (const float*)d_in[2];
    const float* Wq = (const float*)d_in[3];
    const float* bq = (const float*)d_in[4];
    const float* Wk = (const float*)d_in[5];
    const float* bk = (const float*)d_in[6];
    const float* Wv = (const float*)d_in[7];
    const float* bv = (const float*)d_in[8];
    const float* Wo = (const float*)d_in[9];
    const float* bo = (const float*)d_in[10];
    float* out = (float*)d_out;

    float *Qp, *Kp, *Vt, *Attn, *qr, *kr, *vr, *Wqt, *Wkt, *Wvt, *Wot;
    cudaGetSymbolAddress((void**)&Qp,   g_Qp);
    cudaGetSymbolAddress((void**)&Kp,   g_Kp);
    cudaGetSymbolAddress((void**)&Vt,   g_Vt);
    cudaGetSymbolAddress((void**)&Attn, g_Attn);
    cudaGetSymbolAddress((void**)&qr,   g_qr);
    cudaGetSymbolAddress((void**)&kr,   g_kr);
    cudaGetSymbolAddress((void**)&vr,   g_vr);
    cudaGetSymbolAddress((void**)&Wqt,  g_Wqt);
    cudaGetSymbolAddress((void**)&Wkt,  g_Wkt);
    cudaGetSymbolAddress((void**)&Wvt,  g_Wvt);
    cudaGetSymbolAddress((void**)&Wot,  g_Wot);

    cudaFuncSetAttribute(attn_mma_kernel,
                         cudaFuncAttributeMaxDynamicSharedMemorySize,
                         ATTN_SMEM_BYTES);

    const int BIG4 = MROWS * EMBED / 4;
    dim3 rgrid(BIG4 / 256, 3);
    round_inputs<<<rgrid, 256>>>((const float4*)q, (const float4*)k, (const float4*)v,
                                 (float4*)qr, (float4*)kr, (float4*)vr, BIG4);
    dim3 tgrid(EMBED / 32, EMBED / 32, 4);
    dim3 tblk(32, 8);
    transpose_round4<<<tgrid, tblk>>>(Wq, Wk, Wv, Wo, Wqt, Wkt, Wvt, Wot);

    dim3 gemm_grid(EMBED / GBN, MROWS / GBM);   // (8, 32)
    gemm_tf32_bias<1><<<gemm_grid, 128>>>(qr, Wqt, bq, Qp, MROWS, EMBED, EMBED);
    gemm_tf32_bias<1><<<gemm_grid, 128>>>(kr, Wkt, bk, Kp, MROWS, EMBED, EMBED);
    gemm_tf32_bias<2><<<gemm_grid, 128>>>(vr, Wvt, bv, Vt, MROWS, EMBED, EMBED);

    dim3 attn_grid(SEQ / 128, HEADS, BATCH);    // (16, 16, 2)
    attn_mma_kernel<<<attn_grid, 128, ATTN_SMEM_BYTES>>>(Qp, Kp, Vt, Attn);

    gemm_tf32_bias<0><<<gemm_grid, 128>>>(Attn, Wot, bo, out, MROWS, EMBED, EMBED);
}

// round 9
// speedup vs baseline: 8.6949x; 1.8240x over previous
#include <cuda_runtime.h>
#include <cuda_fp16.h>
#include <math.h>
#include <stdint.h>

// Problem constants
#define BATCH 2
#define SEQ   2048
#define EMBED 1024
#define HEADS 16
#define HDIM  64
#define MROWS (BATCH * SEQ)   // 4096

// ---------------- scratch (device globals; no runtime allocation) ----------
__device__ __half g_qh[MROWS * EMBED];
__device__ __half g_kh[MROWS * EMBED];
__device__ __half g_vh[MROWS * EMBED];
__device__ __half g_Wqt[EMBED * EMBED];   // transposed: Wt[n][k] = W[k][n]
__device__ __half g_Wkt[EMBED * EMBED];
__device__ __half g_Wvt[EMBED * EMBED];
__device__ __half g_Wot[EMBED * EMBED];
__device__ __half g_Qp[MROWS * EMBED];    // Q projected (pre-scaled by 1/8*log2e)
__device__ __half g_Kp[MROWS * EMBED];
__device__ __half g_Vt[MROWS * EMBED];    // V projected, [bb][h][d][seq]
__device__ __half g_Ah[MROWS * EMBED];    // attention output (fp16)

// ---------------- helpers ---------------------------------------------------
__device__ __forceinline__ float ex2(float x) {
    float r;
    asm("ex2.approx.f32 %0, %1;" : "=f"(r) : "f"(x));
    return r;
}

__device__ __forceinline__ void cp_async16(void* smem_ptr, const void* gmem_ptr) {
    uint32_t s = (uint32_t)__cvta_generic_to_shared(smem_ptr);
    asm volatile("cp.async.cg.shared.global [%0], [%1], 16;\n" :: "r"(s), "l"(gmem_ptr));
}
#define CP_ASYNC_COMMIT() asm volatile("cp.async.commit_group;\n" ::: "memory")
#define CP_ASYNC_WAIT0()  asm volatile("cp.async.wait_group 0;\n" ::: "memory")
#define CP_ASYNC_WAIT1()  asm volatile("cp.async.wait_group 1;\n" ::: "memory")

// fp16 MMA, fp32 accumulate
__device__ __forceinline__ void mma_f16(float& d0, float& d1, float& d2, float& d3,
                                        uint32_t a0, uint32_t a1, uint32_t a2, uint32_t a3,
                                        uint32_t b0, uint32_t b1) {
    asm volatile(
        "mma.sync.aligned.m16n8k16.row.col.f32.f16.f16.f32 "
        "{%0,%1,%2,%3}, {%4,%5,%6,%7}, {%8,%9}, {%0,%1,%2,%3};\n"
        : "+f"(d0), "+f"(d1), "+f"(d2), "+f"(d3)
        : "r"(a0), "r"(a1), "r"(a2), "r"(a3), "r"(b0), "r"(b1));
}

__device__ __forceinline__ void ldsm_x4(uint32_t& r0, uint32_t& r1,
                                        uint32_t& r2, uint32_t& r3, uint32_t addr) {
    asm volatile("ldmatrix.sync.aligned.m8n8.x4.shared.b16 {%0,%1,%2,%3}, [%4];"
                 : "=r"(r0), "=r"(r1), "=r"(r2), "=r"(r3) : "r"(addr));
}

// ---------------- pre-passes -------------------------------------------------
// Convert q,k,v fp32 -> fp16 (one launch, blockIdx.y selects tensor)
__global__ __launch_bounds__(256)
void cvt_inputs(const float4* __restrict__ q, const float4* __restrict__ k,
                const float4* __restrict__ v,
                __half2* __restrict__ qo, __half2* __restrict__ ko,
                __half2* __restrict__ vo, int n4)
{
    const float4* in  = (blockIdx.y == 0) ? q  : (blockIdx.y == 1) ? k  : v;
    __half2*      out = (blockIdx.y == 0) ? qo : (blockIdx.y == 1) ? ko : vo;
    int i = blockIdx.x * blockDim.x + threadIdx.x;
    if (i < n4) {
        float4 t = in[i];
        out[2 * i]     = __float22half2_rn(make_float2(t.x, t.y));
        out[2 * i + 1] = __float22half2_rn(make_float2(t.z, t.w));
    }
}

// Transpose+convert all 4 weights: T[n][k] = fp16(W[k][n])
__global__ __launch_bounds__(256)
void transpose_h4(const float* __restrict__ W0, const float* __restrict__ W1,
                  const float* __restrict__ W2, const float* __restrict__ W3,
                  __half* __restrict__ T0, __half* __restrict__ T1,
                  __half* __restrict__ T2, __half* __restrict__ T3)
{
    __shared__ float tile[32][33];
    const float* W = (blockIdx.z == 0) ? W0 : (blockIdx.z == 1) ? W1
                   : (blockIdx.z == 2) ? W2 : W3;
    __half* T = (blockIdx.z == 0) ? T0 : (blockIdx.z == 1) ? T1
              : (blockIdx.z == 2) ? T2 : T3;
    const int tx = threadIdx.x;
    const int ty = threadIdx.y;
    const int k0 = blockIdx.x * 32;
    const int n0 = blockIdx.y * 32;
    #pragma unroll
    for (int j = 0; j < 32; j += 8)
        tile[ty + j][tx] = W[(size_t)(k0 + ty + j) * EMBED + n0 + tx];
    __syncthreads();
    #pragma unroll
    for (int j = 0; j < 32; j += 8)
        T[(size_t)(n0 + ty + j) * EMBED + k0 + tx] = __float2half_rn(tile[tx][ty + j]);
}

// ---------------- FP16 tensor-core GEMM: C = A[M,K] @ Bt[N,K]^T + bias ------
// Block tile 128x128, 4 warps (64x64 warp tile), BK=32, m16n8k16 via ldmatrix.
// MODE: 0 = fp32 store; 1 = fp16 store (scale applied); 2 = fp16 store
//       transposed-per-head (Vt[((bb*16+h)*64+d)*2048 + seq])
#define GBK 32
#define G_STRH 40              // halves per tile row (64B data + 16B pad)
#define G_ROWB 80              // bytes
#define G_TILEH (128 * G_STRH)

template<int MODE>
__global__ __launch_bounds__(128, 2)
void gemm_f16(const __half* __restrict__ A,
              const __half* __restrict__ Bt,
              const float* __restrict__ bias,
              void* __restrict__ Cv,
              float scale)
{
    __shared__ __half As[2][G_TILEH];
    __shared__ __half Bs[2][G_TILEH];

    const int tid  = threadIdx.x;
    const int wid  = tid >> 5;
    const int lane = tid & 31;
    const int gi   = lane >> 2;
    const int ti   = lane & 3;
    const int mi   = lane >> 3;
    const int lr   = lane & 7;
    const int K    = EMBED;

    const int brow = blockIdx.y;
    const int bcol = blockIdx.x;
    const int warp_m = (wid & 1) * 64;
    const int warp_n = (wid >> 1) * 64;

    const __half* Ablk = A  + (size_t)(brow * 128) * K;
    const __half* Bblk = Bt + (size_t)(bcol * 128) * K;

    const uint32_t AsU = (uint32_t)__cvta_generic_to_shared(&As[0][0]);
    const uint32_t BsU = (uint32_t)__cvta_generic_to_shared(&Bs[0][0]);
    // a-frag: matrices (rowblk mi&1, kblk mi>>1)
    const uint32_t laneA = (uint32_t)(((mi & 1) * 8 + lr) * G_ROWB + (mi >> 1) * 16);
    // b-frag: matrices (nblk mi>>1, kblk mi&1)
    const uint32_t laneB = (uint32_t)(((mi >> 1) * 8 + lr) * G_ROWB + (mi & 1) * 16);

    float acc[4][8][4];
    #pragma unroll
    for (int i = 0; i < 4; i++)
        #pragma unroll
        for (int j = 0; j < 8; j++)
            #pragma unroll
            for (int r = 0; r < 4; r++) acc[i][j][r] = 0.0f;

    const int NIT = K / GBK;   // 32

    auto load_tile = [&](int buf, int k0) {
        #pragma unroll
        for (int i = 0; i < 4; i++) {
            int f = tid + i * 128;     // 0..511
            int r = f >> 2;            // 0..127
            int c = f & 3;             // 16B chunk
            cp_async16(&As[buf][r * G_STRH + c * 8], Ablk + (size_t)r * K + k0 + c * 8);
            cp_async16(&Bs[buf][r * G_STRH + c * 8], Bblk + (size_t)r * K + k0 + c * 8);
        }
        CP_ASYNC_COMMIT();
    };

    load_tile(0, 0);

    int buf = 0;
    for (int it = 0; it < NIT; it++) {
        CP_ASYNC_WAIT0();
        __syncthreads();
        if (it + 1 < NIT) load_tile(buf ^ 1, (it + 1) * GBK);

        const uint32_t Au = AsU + (uint32_t)buf * (G_TILEH * 2);
        const uint32_t Bu = BsU + (uint32_t)buf * (G_TILEH * 2);
        #pragma unroll
        for (int ks = 0; ks < 2; ks++) {   // two k16 chunks per BK=32
            uint32_t afr[4][4];
            #pragma unroll
            for (int mt = 0; mt < 4; mt++)
                ldsm_x4(afr[mt][0], afr[mt][1], afr[mt][2], afr[mt][3],
                        Au + (uint32_t)((warp_m + mt * 16) * G_ROWB + ks * 32) + laneA);
            uint32_t bfr[8][2];
            #pragma unroll
            for (int p = 0; p < 4; p++)
                ldsm_x4(bfr[2 * p][0], bfr[2 * p][1], bfr[2 * p + 1][0], bfr[2 * p + 1][1],
                        Bu + (uint32_t)((warp_n + p * 16) * G_ROWB + ks * 32) + laneB);
            #pragma unroll
            for (int mt = 0; mt < 4; mt++)
                #pragma unroll
                for (int nt = 0; nt < 8; nt++)
                    mma_f16(acc[mt][nt][0], acc[mt][nt][1],
                            acc[mt][nt][2], acc[mt][nt][3],
                            afr[mt][0], afr[mt][1], afr[mt][2], afr[mt][3],
                            bfr[nt][0], bfr[nt][1]);
        }
        buf ^= 1;
        __syncthreads();
    }

    #pragma unroll
    for (int mt = 0; mt < 4; mt++) {
        int row0 = brow * 128 + warp_m + mt * 16 + gi;
        #pragma unroll
        for (int nt = 0; nt < 8; nt++) {
            int col0 = bcol * 128 + warp_n + nt * 8 + 2 * ti;
            float b0 = bias[col0], b1 = bias[col0 + 1];
            float c00 = (acc[mt][nt][0] + b0) * scale, c01 = (acc[mt][nt][1] + b1) * scale;
            float c10 = (acc[mt][nt][2] + b0) * scale, c11 = (acc[mt][nt][3] + b1) * scale;
            if (MODE == 0) {
                float* C = (float*)Cv;
                *(float2*)(C + (size_t)row0 * EMBED + col0)       = make_float2(c00, c01);
                *(float2*)(C + (size_t)(row0 + 8) * EMBED + col0) = make_float2(c10, c11);
            } else if (MODE == 1) {
                __half* C = (__half*)Cv;
                *(__half2*)(C + (size_t)row0 * EMBED + col0) =
                    __float22half2_rn(make_float2(c00, c01));
                *(__half2*)(C + (size_t)(row0 + 8) * EMBED + col0) =
                    __float22half2_rn(make_float2(c10, c11));
            } else {
                // Vt[((bb*16+h)*64 + d)*2048 + seq]
                __half* C = (__half*)Cv;
                int h  = col0 >> 6;
                int d0 = col0 & 63;
                #pragma unroll
                for (int rr = 0; rr < 2; rr++) {
                    int row = row0 + rr * 8;
                    int bb  = row >> 11, seq = row & 2047;
                    size_t base = ((size_t)((bb * HEADS + h) * HDIM)) * SEQ + seq;
                    C[base + (size_t)d0 * SEQ]       = __float2half_rn(rr ? c10 : c00);
                    C[base + (size_t)(d0 + 1) * SEQ] = __float2half_rn(rr ? c11 : c01);
                }
            }
        }
    }
}

// ---------------- FP16 mma flash attention ----------------------------------
// 4 warps, 32 Q rows/warp, 64-key tiles, everything through ldmatrix.
#define A_STRH  72              // halves per row (128B data + 16B pad)
#define A_ROWB  144
#define KS_TILEH (64 * A_STRH)
#define VT_TILEH (64 * A_STRH)
#define PB_H     (128 * A_STRH)
#define ATTN_SMEM_BYTES ((2 * KS_TILEH + 2 * VT_TILEH + PB_H) * 2)

__global__ __launch_bounds__(128, 2)
void attn_f16_kernel(const __half* __restrict__ Qp,
                     const __half* __restrict__ Kp,
                     const __half* __restrict__ Vt,
                     __half* __restrict__ Out)
{
    extern __shared__ __half smh[];
    __half* KsBuf = smh;
    __half* VsBuf = smh + 2 * KS_TILEH;
    __half* Pb    = smh + 2 * KS_TILEH + 2 * VT_TILEH;

    const int tid  = threadIdx.x;
    const int wid  = tid >> 5;
    const int lane = tid & 31;
    const int gi   = lane >> 2;
    const int ti   = lane & 3;
    const int mi   = lane >> 3;
    const int lr   = lane & 7;
    const int h    = blockIdx.y;
    const int bb   = blockIdx.z;
    const int q0   = blockIdx.x * 128;

    const __half* Qbase  = Qp + ((size_t)(bb * SEQ + q0)) * EMBED + h * HDIM;
    const __half* Kbase  = Kp + ((size_t)bb * SEQ) * EMBED + h * HDIM;
    const __half* Vtbase = Vt + ((size_t)((bb * HEADS + h) * HDIM)) * SEQ;  // [64][2048]

    const uint32_t KsU = (uint32_t)__cvta_generic_to_shared(KsBuf);
    const uint32_t VsU = (uint32_t)__cvta_generic_to_shared(VsBuf);
    const uint32_t PbU = (uint32_t)__cvta_generic_to_shared(Pb);
    const uint32_t PwU = PbU + (uint32_t)((wid * 32) * A_ROWB);
    const uint32_t laneKB = (uint32_t)(lr * A_ROWB + mi * 16);           // b-frags (K,V)
    const uint32_t lanePA = (uint32_t)(((mi & 1) * 8 + lr) * A_ROWB + (mi >> 1) * 16); // a-frags

    // ---- stage Q tile [128 x 64 halves] into Pb ----
    #pragma unroll
    for (int i = 0; i < 8; i++) {
        int f = tid + i * 128;          // 0..1023
        int r = f >> 3, c = f & 7;
        cp_async16(&Pb[r * A_STRH + c * 8], Qbase + (size_t)r * EMBED + c * 8);
    }
    CP_ASYNC_COMMIT();
    CP_ASYNC_WAIT0();
    __syncthreads();

    // Q a-frags via ldmatrix (scale already folded in at projection time)
    uint32_t qf[2][4][4];
    #pragma unroll
    for (int mt = 0; mt < 2; mt++)
        #pragma unroll
        for (int ks = 0; ks < 4; ks++)
            ldsm_x4(qf[mt][ks][0], qf[mt][ks][1], qf[mt][ks][2], qf[mt][ks][3],
                    PwU + (uint32_t)(mt * 16 * A_ROWB + ks * 32) + lanePA);
    __syncthreads();   // Pb now free for P

    float oacc[2][8][4];
    #pragma unroll
    for (int mt = 0; mt < 2; mt++)
        #pragma unroll
        for (int nt = 0; nt < 8; nt++)
            #pragma unroll
            for (int r = 0; r < 4; r++) oacc[mt][nt][r] = 0.0f;
    float mA[2] = {-1e30f, -1e30f}, mB[2] = {-1e30f, -1e30f};
    float lA[2] = {0.0f, 0.0f},     lB[2] = {0.0f, 0.0f};

    auto load_kv = [&](int t, int b) {
        const __half* Kt = Kbase + (size_t)(t * 64) * EMBED;
        const __half* Vg = Vtbase + t * 64;
        __half* Kd = KsBuf + b * KS_TILEH;
        __half* Vd = VsBuf + b * VT_TILEH;
        #pragma unroll
        for (int i = 0; i < 4; i++) {
            int f = tid + i * 128;      // 0..511
            int r = f >> 3, c = f & 7;
            cp_async16(&Kd[r * A_STRH + c * 8], Kt + (size_t)r * EMBED + c * 8);
            cp_async16(&Vd[r * A_STRH + c * 8], Vg + (size_t)r * SEQ + c * 8);
        }
        CP_ASYNC_COMMIT();
    };

    const int NT = SEQ / 64;
    load_kv(0, 0);
    int buf = 0;

    __half* Pw = Pb + (wid * 32) * A_STRH;

    for (int t = 0; t < NT; t++) {
        if (t + 1 < NT) {
            load_kv(t + 1, buf ^ 1);
            CP_ASYNC_WAIT1();
        } else {
            CP_ASYNC_WAIT0();
        }
        __syncthreads();

        const uint32_t KdU = KsU + (uint32_t)(buf * KS_TILEH * 2);
        const uint32_t VdU = VsU + (uint32_t)(buf * VT_TILEH * 2);

        // ---- S = Q K^T : 64 MMAs (2 mt x 8 nt x 4 ks) ----
        float s[2][8][4];
        #pragma unroll
        for (int nt = 0; nt < 8; nt++) {
            uint32_t kb[8];
            uint32_t base = KdU + (uint32_t)(nt * 8 * A_ROWB) + laneKB;
            ldsm_x4(kb[0], kb[1], kb[2], kb[3], base);
            ldsm_x4(kb[4], kb[5], kb[6], kb[7], base + 64);
            #pragma unroll
            for (int r = 0; r < 4; r++) { s[0][nt][r] = 0.0f; s[1][nt][r] = 0.0f; }
            #pragma unroll
            for (int ks = 0; ks < 4; ks++) {
                mma_f16(s[0][nt][0], s[0][nt][1], s[0][nt][2], s[0][nt][3],
                        qf[0][ks][0], qf[0][ks][1], qf[0][ks][2], qf[0][ks][3],
                        kb[2 * ks], kb[2 * ks + 1]);
                mma_f16(s[1][nt][0], s[1][nt][1], s[1][nt][2], s[1][nt][3],
                        qf[1][ks][0], qf[1][ks][1], qf[1][ks][2], qf[1][ks][3],
                        kb[2 * ks], kb[2 * ks + 1]);
            }
        }

        // ---- online softmax per m-tile ----
        #pragma unroll
        for (int mt = 0; mt < 2; mt++) {
            float mAt = -1e30f, mBt = -1e30f;
            #pragma unroll
            for (int nt = 0; nt < 8; nt++) {
                mAt = fmaxf(mAt, fmaxf(s[mt][nt][0], s[mt][nt][1]));
                mBt = fmaxf(mBt, fmaxf(s[mt][nt][2], s[mt][nt][3]));
            }
            mAt = fmaxf(mAt, __shfl_xor_sync(0xffffffffu, mAt, 1));
            mAt = fmaxf(mAt, __shfl_xor_sync(0xffffffffu, mAt, 2));
            mBt = fmaxf(mBt, __shfl_xor_sync(0xffffffffu, mBt, 1));
            mBt = fmaxf(mBt, __shfl_xor_sync(0xffffffffu, mBt, 2));

            float mA_new = fmaxf(mA[mt], mAt), mB_new = fmaxf(mB[mt], mBt);
            float cA = ex2(mA[mt] - mA_new), cB = ex2(mB[mt] - mB_new);

            float sA = 0.0f, sB = 0.0f;
            int rlo = mt * 16 + gi, rhi = rlo + 8;
            #pragma unroll
            for (int nt = 0; nt < 8; nt++) {
                float p0 = ex2(s[mt][nt][0] - mA_new);
                float p1 = ex2(s[mt][nt][1] - mA_new);
                float p2 = ex2(s[mt][nt][2] - mB_new);
                float p3 = ex2(s[mt][nt][3] - mB_new);
                sA += p0 + p1; sB += p2 + p3;
                *(__half2*)&Pw[rlo * A_STRH + nt * 8 + 2 * ti] =
                    __float22half2_rn(make_float2(p0, p1));
                *(__half2*)&Pw[rhi * A_STRH + nt * 8 + 2 * ti] =
                    __float22half2_rn(make_float2(p2, p3));
            }
            sA += __shfl_xor_sync(0xffffffffu, sA, 1);
            sA += __shfl_xor_sync(0xffffffffu, sA, 2);
            sB += __shfl_xor_sync(0xffffffffu, sB, 1);
            sB += __shfl_xor_sync(0xffffffffu, sB, 2);

            lA[mt] = lA[mt] * cA + sA;
            lB[mt] = lB[mt] * cB + sB;
            mA[mt] = mA_new; mB[mt] = mB_new;

            #pragma unroll
            for (int nt = 0; nt < 8; nt++) {
                oacc[mt][nt][0] *= cA; oacc[mt][nt][1] *= cA;
                oacc[mt][nt][2] *= cB; oacc[mt][nt][3] *= cB;
            }
        }
        __syncwarp();

        // ---- O += P V : P a-frags (8 LDSM), V b-frags (16 LDSM), 64 MMAs ----
        uint32_t pa[2][4][4];
        #pragma unroll
        for (int mt = 0; mt < 2; mt++)
            #pragma unroll
            for (int ks = 0; ks < 4; ks++)
                ldsm_x4(pa[mt][ks][0], pa[mt][ks][1], pa[mt][ks][2], pa[mt][ks][3],
                        PwU + (uint32_t)(mt * 16 * A_ROWB + ks * 32) + lanePA);

        #pragma unroll
        for (int nt = 0; nt < 8; nt++) {      // output-dim group (rows of Vt)
            uint32_t vb[8];
            uint32_t base = VdU + (uint32_t)(nt * 8 * A_ROWB) + laneKB;
            ldsm_x4(vb[0], vb[1], vb[2], vb[3], base);
            ldsm_x4(vb[4], vb[5], vb[6], vb[7], base + 64);
            #pragma unroll
            for (int ks = 0; ks < 4; ks++) {
                mma_f16(oacc[0][nt][0], oacc[0][nt][1], oacc[0][nt][2], oacc[0][nt][3],
                        pa[0][ks][0], pa[0][ks][1], pa[0][ks][2], pa[0][ks][3],
                        vb[2 * ks], vb[2 * ks + 1]);
                mma_f16(oacc[1][nt][0], oacc[1][nt][1], oacc[1][nt][2], oacc[1][nt][3],
                        pa[1][ks][0], pa[1][ks][1], pa[1][ks][2], pa[1][ks][3],
                        vb[2 * ks], vb[2 * ks + 1]);
            }
        }
        __syncthreads();
        buf ^= 1;
    }

    // ---- epilogue: normalize + fp16 store (feeds O-projection) ----
    #pragma unroll
    for (int mt = 0; mt < 2; mt++) {
        const float invA = 1.0f / lA[mt], invB = 1.0f / lB[mt];
        const int row0 = q0 + wid * 32 + mt * 16 + gi;
        __half* Ob = Out + ((size_t)(bb * SEQ + row0)) * EMBED + h * HDIM;
        #pragma unroll
        for (int nt = 0; nt < 8; nt++) {
            int col = nt * 8 + 2 * ti;
            *(__half2*)(Ob + col) = __float22half2_rn(
                make_float2(oacc[mt][nt][0] * invA, oacc[mt][nt][1] * invA));
            *(__half2*)(Ob + (size_t)8 * EMBED + col) = __float22half2_rn(
                make_float2(oacc[mt][nt][2] * invB, oacc[mt][nt][3] * invB));
        }
    }
}

// ---------------- launch ----------------------------------------------------
extern "C" void kernel_launch(void* const* d_in, const int* in_sizes, int n_in,
                              void* d_out, int out_size)
{
    const float* q  = (const float*)d_in[0];
    const float* k  = (const float*)d_in[1];
    const float* v  = (const float*)d_in[2];
    const float* Wq = (const float*)d_in[3];
    const float* bq = (const float*)d_in[4];
    const float* Wk = (const float*)d_in[5];
    const float* bk = (const float*)d_in[6];
    const float* Wv = (const float*)d_in[7];
    const float* bv = (const float*)d_in[8];
    const float* Wo = (const float*)d_in[9];
    const float* bo = (const float*)d_in[10];
    float* out = (float*)d_out;

    __half *qh, *kh, *vh, *Wqt, *Wkt, *Wvt, *Wot, *Qp, *Kp, *Vt, *Ah;
    cudaGetSymbolAddress((void**)&qh,  g_qh);
    cudaGetSymbolAddress((void**)&kh,  g_kh);
    cudaGetSymbolAddress((void**)&vh,  g_vh);
    cudaGetSymbolAddress((void**)&Wqt, g_Wqt);
    cudaGetSymbolAddress((void**)&Wkt, g_Wkt);
    cudaGetSymbolAddress((void**)&Wvt, g_Wvt);
    cudaGetSymbolAddress((void**)&Wot, g_Wot);
    cudaGetSymbolAddress((void**)&Qp,  g_Qp);
    cudaGetSymbolAddress((void**)&Kp,  g_Kp);
    cudaGetSymbolAddress((void**)&Vt,  g_Vt);
    cudaGetSymbolAddress((void**)&Ah,  g_Ah);

    cudaFuncSetAttribute(attn_f16_kernel,
                         cudaFuncAttributeMaxDynamicSharedMemorySize,
                         ATTN_SMEM_BYTES);

    const int BIG4 = MROWS * EMBED / 4;
    dim3 rgrid(BIG4 / 256, 3);
    cvt_inputs<<<rgrid, 256>>>((const float4*)q, (const float4*)k, (const float4*)v,
                               (__half2*)qh, (__half2*)kh, (__half2*)vh, BIG4);
    dim3 tgrid(EMBED / 32, EMBED / 32, 4);
    dim3 tblk(32, 8);
    transpose_h4<<<tgrid, tblk>>>(Wq, Wk, Wv, Wo, Wqt, Wkt, Wvt, Wot);

    const float qscale = 0.125f * 1.4426950408889634f;   // 1/sqrt(64) * log2(e)
    dim3 gemm_grid(EMBED / 128, MROWS / 128);   // (8, 32)
    gemm_f16<1><<<gemm_grid, 128>>>(qh, Wqt, bq, Qp, qscale);
    gemm_f16<1><<<gemm_grid, 128>>>(kh, Wkt, bk, Kp, 1.0f);
    gemm_f16<2><<<gemm_grid, 128>>>(vh, Wvt, bv, Vt, 1.0f);

    dim3 attn_grid(SEQ / 128, HEADS, BATCH);    // (16, 16, 2)
    attn_f16_kernel<<<attn_grid, 128, ATTN_SMEM_BYTES>>>(Qp, Kp, Vt, Ah);

    gemm_f16<0><<<gemm_grid, 128>>>(Ah, Wot, bo, out, 1.0f);
}